// round 4
// baseline (speedup 1.0000x reference)
#include <cuda_runtime.h>
#include <math.h>

#define Bb 16
#define Ss 128
#define Nn 64
#define Ee 128
#define Hh 128
#define Ll 32

// ---------------------------------------------------------------------------
// Device-global scratch (no runtime allocation allowed)
// ---------------------------------------------------------------------------
__device__ float g_Xg[(size_t)2 * Bb * Ss * 4 * Hh];   // (dir,b,t,512)
__device__ float g_Xl[(size_t)2 * Bb * Ss * Hh];       // (dir,b,t,128)
__device__ float g_Wg[(size_t)2 * Bb * Nn * 3 * Hh];   // (dir,b,n,384)
__device__ float g_WwhT[(size_t)2 * 3 * Hh * Hh];      // (dir,k(384),j(128)) transposed
__device__ float g_WlcT[(size_t)2 * Hh * Hh];          // (dir,k(128),j(128)) transposed
__device__ float g_feats[(size_t)Bb * Ss * 2 * Hh];    // (b,t,256)
__device__ float g_logits[(size_t)Bb * Ss * Ll];
__device__ float g_pb[Bb];

__device__ __forceinline__ float sigf(float x) { return 1.f / (1.f + expf(-x)); }

// ---------------------------------------------------------------------------
// Prep: transpose Wwh (128x384 -> 384x128) and Wlc (128x128 -> T), both dirs
// ---------------------------------------------------------------------------
__global__ void prep_transpose_kernel(const float* __restrict__ fWwh,
                                      const float* __restrict__ rWwh,
                                      const float* __restrict__ fWlc,
                                      const float* __restrict__ rWlc)
{
    int which = blockIdx.y;
    const float* in;
    float* out;
    int K;
    if (which == 0)      { in = fWwh; out = g_WwhT;               K = 384; }
    else if (which == 1) { in = rWwh; out = g_WwhT + 384 * 128;   K = 384; }
    else if (which == 2) { in = fWlc; out = g_WlcT;               K = 128; }
    else                 { in = rWlc; out = g_WlcT + 128 * 128;   K = 128; }
    int idx = blockIdx.x * 256 + threadIdx.x;
    if (idx < K * 128) {
        int k = idx >> 7;
        int j = idx & 127;
        out[idx] = in[j * K + k];   // out[k*128+j]
    }
}

// ---------------------------------------------------------------------------
// Fused char-side gather GEMM (unchanged)
// ---------------------------------------------------------------------------
__global__ void __launch_bounds__(256) char_gather_kernel(
    const float* __restrict__ emb, const int* __restrict__ ids,
    const float* __restrict__ fWcx, const float* __restrict__ rWcx,
    const float* __restrict__ fWlx, const float* __restrict__ rWlx,
    const float* __restrict__ fbc, const float* __restrict__ rbc,
    const float* __restrict__ fbl, const float* __restrict__ rbl)
{
    __shared__ float xs[8][128];
    int b = blockIdx.x, r0 = blockIdx.y * 8, tid = threadIdx.x;

    for (int idx = tid; idx < 8 * 128; idx += 256) {
        int r = idx >> 7, e = idx & 127;
        int id = ids[b * Ss + r0 + r];
        xs[r][e] = emb[(size_t)id * 128 + e];
    }
    __syncthreads();

    const float* wp[5];
    float bias[5];
    float* op[5];
    int ostep[5];

    wp[0] = fWcx + tid;        bias[0] = fbc[tid];
    wp[1] = fWcx + tid + 256;  bias[1] = fbc[tid + 256];
    op[0] = g_Xg + ((size_t)b * Ss + r0) * 512 + tid;
    op[1] = op[0] + 256;
    ostep[0] = ostep[1] = 512;
    wp[2] = rWcx + tid;        bias[2] = rbc[tid];
    wp[3] = rWcx + tid + 256;  bias[3] = rbc[tid + 256];
    op[2] = g_Xg + ((size_t)(Bb + b) * Ss + (Ss - 1 - r0)) * 512 + tid;
    op[3] = op[2] + 256;
    ostep[2] = ostep[3] = -512;
    if (tid < 128) {
        wp[4] = fWlx + tid; bias[4] = fbl[tid];
        op[4] = g_Xl + ((size_t)b * Ss + r0) * 128 + tid;
        ostep[4] = 128;
    } else {
        int c = tid - 128;
        wp[4] = rWlx + c; bias[4] = rbl[c];
        op[4] = g_Xl + ((size_t)(Bb + b) * Ss + (Ss - 1 - r0)) * 128 + c;
        ostep[4] = -128;
    }

    float acc[8][5];
#pragma unroll
    for (int r = 0; r < 8; r++)
#pragma unroll
        for (int s = 0; s < 5; s++) acc[r][s] = 0.f;

    for (int e = 0; e < 128; e++) {
        float w0 = wp[0][(size_t)e * 512];
        float w1 = wp[1][(size_t)e * 512];
        float w2 = wp[2][(size_t)e * 512];
        float w3 = wp[3][(size_t)e * 512];
        float w4 = wp[4][(size_t)e * 128];
#pragma unroll
        for (int r = 0; r < 8; r++) {
            float x = xs[r][e];
            acc[r][0] = fmaf(x, w0, acc[r][0]);
            acc[r][1] = fmaf(x, w1, acc[r][1]);
            acc[r][2] = fmaf(x, w2, acc[r][2]);
            acc[r][3] = fmaf(x, w3, acc[r][3]);
            acc[r][4] = fmaf(x, w4, acc[r][4]);
        }
    }

#pragma unroll
    for (int r = 0; r < 8; r++)
#pragma unroll
        for (int s = 0; s < 5; s++)
            op[s][(long)r * ostep[s]] = acc[r][s] + bias[s];
}

// ---------------------------------------------------------------------------
// Fused kb-side gather GEMM (unchanged)
// ---------------------------------------------------------------------------
__global__ void __launch_bounds__(256) kb_gather_kernel(
    const float* __restrict__ emb, const int* __restrict__ ids,
    const float* __restrict__ fW, const float* __restrict__ rW,
    const float* __restrict__ fb, const float* __restrict__ rb)
{
    __shared__ float xs[8][128];
    int b = blockIdx.x, r0 = blockIdx.y * 8, tid = threadIdx.x;

    for (int idx = tid; idx < 8 * 128; idx += 256) {
        int r = idx >> 7, e = idx & 127;
        int id = ids[b * Nn + r0 + r];
        xs[r][e] = emb[(size_t)id * 128 + e];
    }
    __syncthreads();

    const float* wp[3];
    float bias[3];
    float* op[3];
#pragma unroll
    for (int s = 0; s < 3; s++) {
        int c = tid + 256 * s;
        if (c < 384) {
            wp[s] = fW + c; bias[s] = fb[c];
            op[s] = g_Wg + ((size_t)b * Nn + r0) * 384 + c;
        } else {
            int c2 = c - 384;
            wp[s] = rW + c2; bias[s] = rb[c2];
            op[s] = g_Wg + ((size_t)(Bb + b) * Nn + r0) * 384 + c2;
        }
    }

    float acc[8][3];
#pragma unroll
    for (int r = 0; r < 8; r++)
#pragma unroll
        for (int s = 0; s < 3; s++) acc[r][s] = 0.f;

    for (int e = 0; e < 128; e++) {
        float w0 = wp[0][(size_t)e * 384];
        float w1 = wp[1][(size_t)e * 384];
        float w2 = wp[2][(size_t)e * 384];
#pragma unroll
        for (int r = 0; r < 8; r++) {
            float x = xs[r][e];
            acc[r][0] = fmaf(x, w0, acc[r][0]);
            acc[r][1] = fmaf(x, w1, acc[r][1]);
            acc[r][2] = fmaf(x, w2, acc[r][2]);
        }
    }

#pragma unroll
    for (int r = 0; r < 8; r++)
#pragma unroll
        for (int s = 0; s < 3; s++)
            op[s][(size_t)r * 384] = acc[r][s] + bias[s];
}

// ---------------------------------------------------------------------------
// Warp-specialized lattice LSTM. One CTA per (dir,batch). 640 threads.
//   threads 0-511  : char-gate matvec (48 Wch rows in regs, 80 in smem)
//   threads 512-639: word path (runs concurrently) + cell/state update
// Register cap at 640 threads = 102; char live set ~75, word ~90 -> no spill.
// ---------------------------------------------------------------------------
#define RREG 48
#define RSM  80
#define NTHR 640

// smem float offsets
#define OFF_W   0                      // 80*512 = 40960
#define OFF_H   40960                  // 8*128
#define OFF_C   41984                  // 8*128
#define OFF_G   43008                  // 512
#define OFF_CW  43520                  // 128
#define OFF_SE  43648                  // 128
#define OFF_SC  43776                  // 128
#define FLT_END 43904
// ints: w_beg[64], w_end[64], wl_start[129], wl_idx[64], cur[128]
#define INT_CNT 449
#define SMEM_LAT (FLT_END * 4 + INT_CNT * 4)

__global__ void __launch_bounds__(NTHR, 1) lattice_kernel(
    const float* __restrict__ Wch_f, const float* __restrict__ Wch_r,
    const int* __restrict__ word_begin, const int* __restrict__ word_len,
    const int* __restrict__ seqlen)
{
    extern __shared__ float sm[];
    float* wsm      = sm + OFF_W;
    float* h_ring   = sm + OFF_H;
    float* c_ring   = sm + OFF_C;
    float* gates    = sm + OFF_G;
    float* cw       = sm + OFF_CW;
    float* sum_ew   = sm + OFF_SE;
    float* sum_ewcw = sm + OFF_SC;
    int* ip        = (int*)(sm + FLT_END);
    int* w_beg     = ip;
    int* w_end     = ip + 64;
    int* wl_start  = ip + 128;     // 129 entries
    int* wl_idx    = ip + 257;     // 64
    int* cur       = ip + 321;     // 128

    int dirb = blockIdx.x;
    int dir  = dirb / Bb;
    int b    = dirb - dir * Bb;
    int tid  = threadIdx.x;
    int sl   = seqlen[b];

    const float* Wch  = dir ? Wch_r : Wch_f;
    const float* WwhT = g_WwhT + (size_t)dir * 384 * 128;
    const float* WlcT = g_WlcT + (size_t)dir * 128 * 128;
    const float* Xg_b = g_Xg + (size_t)dirb * Ss * 512;
    const float* Xl_b = g_Xl + (size_t)dirb * Ss * 128;
    const float* Wg_b = g_Wg + (size_t)dirb * Nn * 384;

    // smem weight rows loaded by everyone
    for (int i = tid; i < RSM * 512; i += NTHR) {
        int r = i >> 9, c = i & 511;
        wsm[i] = Wch[(size_t)(RREG + r) * 512 + c];
    }

    // register-resident weight rows (char threads only)
    float wreg[RREG];
    if (tid < 512) {
#pragma unroll
        for (int r = 0; r < RREG; r++) wreg[r] = Wch[(size_t)r * 512 + tid];
    }

    if (tid >= 512) {
        int k = tid - 512;
        h_ring[k] = 0.f;
        c_ring[k] = 0.f;
    }

    if (tid < Nn) {
        int bg = word_begin[b * Nn + tid];
        int ln = word_len[b * Nn + tid];
        int ef = min(bg + ln, Ss - 1);
        bool valid = ef < sl;
        if (dir == 0) {
            w_beg[tid] = bg;
            w_end[tid] = valid ? ef : -1;
        } else {
            w_beg[tid] = Ss - 1 - ef;
            w_end[tid] = valid ? (Ss - 1 - bg) : -1;
        }
    }
    __syncthreads();

    if (tid == 0) {
        for (int t = 0; t < Ss; t++) cur[t] = 0;
        for (int n = 0; n < Nn; n++) { int e = w_end[n]; if (e >= 0) cur[e]++; }
        wl_start[0] = 0;
        for (int t = 0; t < Ss; t++) wl_start[t + 1] = wl_start[t] + cur[t];
        for (int t = 0; t < Ss; t++) cur[t] = wl_start[t];
        for (int n = 0; n < Nn; n++) { int e = w_end[n]; if (e >= 0) wl_idx[cur[e]++] = n; }
    }
    __syncthreads();

    for (int t = 0; t < Ss; t++) {
        int curS = (t & 7) * Hh;
        int nxtS = ((t + 1) & 7) * Hh;
        bool valid = (dir == 0) ? (t < sl) : (t >= Ss - sl);

        if (!valid) {
            if (tid >= 512) {
                int k = tid - 512;
                h_ring[nxtS + k] = h_ring[curS + k];
                c_ring[nxtS + k] = c_ring[curS + k];
                int tt = (dir == 0) ? t : (Ss - 1 - t);
                g_feats[((size_t)b * Ss + tt) * (2 * Hh) + dir * Hh + k] = 0.f;
            }
            __syncthreads();
            continue;
        }

        int wls = wl_start[t];
        int m = wl_start[t + 1] - wls;

        if (tid < 512) {
            // ---- char gate matvec (concurrent with word path) ----
            const float4* h4 = (const float4*)(h_ring + curS);
            float a0 = Xg_b[(size_t)t * 512 + tid];
            float a1 = 0.f;
#pragma unroll
            for (int q = 0; q < 12; q += 2) {
                float4 v0 = h4[q], v1 = h4[q + 1];
                a0 = fmaf(v0.x, wreg[4 * q + 0], a0);
                a0 = fmaf(v0.y, wreg[4 * q + 1], a0);
                a0 = fmaf(v0.z, wreg[4 * q + 2], a0);
                a0 = fmaf(v0.w, wreg[4 * q + 3], a0);
                a1 = fmaf(v1.x, wreg[4 * q + 4], a1);
                a1 = fmaf(v1.y, wreg[4 * q + 5], a1);
                a1 = fmaf(v1.z, wreg[4 * q + 6], a1);
                a1 = fmaf(v1.w, wreg[4 * q + 7], a1);
            }
#pragma unroll
            for (int q = 0; q < 20; q += 2) {
                float4 v0 = h4[12 + q], v1 = h4[13 + q];
                a0 = fmaf(v0.x, wsm[(4 * q + 0) * 512 + tid], a0);
                a0 = fmaf(v0.y, wsm[(4 * q + 1) * 512 + tid], a0);
                a0 = fmaf(v0.z, wsm[(4 * q + 2) * 512 + tid], a0);
                a0 = fmaf(v0.w, wsm[(4 * q + 3) * 512 + tid], a0);
                a1 = fmaf(v1.x, wsm[(4 * q + 4) * 512 + tid], a1);
                a1 = fmaf(v1.y, wsm[(4 * q + 5) * 512 + tid], a1);
                a1 = fmaf(v1.z, wsm[(4 * q + 6) * 512 + tid], a1);
                a1 = fmaf(v1.w, wsm[(4 * q + 7) * 512 + tid], a1);
            }
            gates[tid] = a0 + a1;
        } else if (m > 0) {
            // ---- word path on 128 dedicated threads ----
            int wt = tid - 512;
            sum_ew[wt] = 0.f;
            sum_ewcw[wt] = 0.f;
            for (int wv = 0; wv < m; wv++) {
                int n   = wl_idx[wls + wv];
                int bgS = (w_beg[n] & 7) * Hh;
                // Wwh matvec: this thread owns gate columns wt, wt+128, wt+256
                const float4* hb4 = (const float4*)(h_ring + bgS);
                const float4* w0  = (const float4*)(WwhT + (size_t)wt * 128);
                const float4* w1  = (const float4*)(WwhT + (size_t)(wt + 128) * 128);
                const float4* w2  = (const float4*)(WwhT + (size_t)(wt + 256) * 128);
                float acc0 = Wg_b[(size_t)n * 384 + wt];
                float acc1 = Wg_b[(size_t)n * 384 + wt + 128];
                float acc2 = Wg_b[(size_t)n * 384 + wt + 256];
#pragma unroll 4
                for (int j = 0; j < 32; j++) {
                    float4 hv = hb4[j];
                    float4 x0 = w0[j], x1 = w1[j], x2 = w2[j];
                    acc0 = fmaf(hv.x, x0.x, acc0);
                    acc0 = fmaf(hv.y, x0.y, acc0);
                    acc0 = fmaf(hv.z, x0.z, acc0);
                    acc0 = fmaf(hv.w, x0.w, acc0);
                    acc1 = fmaf(hv.x, x1.x, acc1);
                    acc1 = fmaf(hv.y, x1.y, acc1);
                    acc1 = fmaf(hv.z, x1.z, acc1);
                    acc1 = fmaf(hv.w, x1.w, acc1);
                    acc2 = fmaf(hv.x, x2.x, acc2);
                    acc2 = fmaf(hv.y, x2.y, acc2);
                    acc2 = fmaf(hv.z, x2.z, acc2);
                    acc2 = fmaf(hv.w, x2.w, acc2);
                }
                // all three gate values are thread-local: no smem exchange needed
                cw[wt] = sigf(acc1) * c_ring[bgS + wt] + sigf(acc0) * tanhf(acc2);
                asm volatile("bar.sync 1, 128;" ::: "memory");   // cw visible
                // Wlc matvec: column wt
                const float4* c4  = (const float4*)cw;
                const float4* wl4 = (const float4*)(WlcT + (size_t)wt * 128);
                float p0 = 0.f, p1 = 0.f;
#pragma unroll 4
                for (int j = 0; j < 32; j += 2) {
                    float4 cv0 = c4[j],     y0 = wl4[j];
                    float4 cv1 = c4[j + 1], y1 = wl4[j + 1];
                    p0 = fmaf(cv0.x, y0.x, p0);
                    p0 = fmaf(cv0.y, y0.y, p0);
                    p0 = fmaf(cv0.z, y0.z, p0);
                    p0 = fmaf(cv0.w, y0.w, p0);
                    p1 = fmaf(cv1.x, y1.x, p1);
                    p1 = fmaf(cv1.y, y1.y, p1);
                    p1 = fmaf(cv1.z, y1.z, p1);
                    p1 = fmaf(cv1.w, y1.w, p1);
                }
                float ew = expf(sigf(Xl_b[(size_t)t * 128 + wt] + p0 + p1));
                sum_ew[wt]   += ew;
                sum_ewcw[wt] += ew * cw[wt];
                asm volatile("bar.sync 1, 128;" ::: "memory");   // cw reusable
            }
        }
        __syncthreads();   // gates + word sums ready

        // ---- cell/state update (word threads) ----
        if (tid >= 512) {
            int k = tid - 512;
            float ig = sigf(gates[k]);
            float fg = sigf(gates[Hh + k]);
            float og = sigf(gates[2 * Hh + k]);
            float gg = tanhf(gates[3 * Hh + k]);
            float cp = c_ring[curS + k];
            float ct;
            if (m > 0) {
                float ec = expf(ig);
                ct = (ec * gg + sum_ewcw[k]) / (ec + sum_ew[k]);
            } else {
                ct = fg * cp + ig * gg;
            }
            float ht = og * tanhf(ct);
            h_ring[nxtS + k] = ht;
            c_ring[nxtS + k] = ct;
            int tt = (dir == 0) ? t : (Ss - 1 - t);
            g_feats[((size_t)b * Ss + tt) * (2 * Hh) + dir * Hh + k] = ht;
        }
        __syncthreads();   // new state visible for next step
    }
}

// ---------------------------------------------------------------------------
// Dense projection
// ---------------------------------------------------------------------------
__global__ void dense_kernel(const float* __restrict__ W, const float* __restrict__ bias)
{
    __shared__ float fs[8][2 * Hh];
    int row0 = blockIdx.x * 8;
    int tid = threadIdx.x;
    for (int idx = tid; idx < 8 * 2 * Hh; idx += 256) {
        int r = idx >> 8;
        int e = idx & 255;
        fs[r][e] = g_feats[(size_t)(row0 + r) * (2 * Hh) + e];
    }
    __syncthreads();
    int r = tid >> 5;
    int col = tid & 31;
    float acc = bias[col];
#pragma unroll 8
    for (int e = 0; e < 2 * Hh; e++) acc = fmaf(fs[r][e], W[e * Ll + col], acc);
    g_logits[(size_t)(row0 + r) * Ll + col] = acc;
}

// ---------------------------------------------------------------------------
// CRF
// ---------------------------------------------------------------------------
__global__ void crf_kernel(const int* __restrict__ label,
                           const int* __restrict__ seqlen,
                           const float* __restrict__ T)
{
    int b = blockIdx.x;
    int j = threadIdx.x;
    int sl = seqlen[b];
    const float* lg = g_logits + (size_t)b * Ss * Ll;
    const int*   lab = label + b * Ss;

    float Tc[32];
#pragma unroll
    for (int i = 0; i < 32; i++) Tc[i] = T[i * Ll + j];

    float gold = 0.f;
    for (int t = j; t < Ss; t += 32)
        if (t < sl) gold += lg[t * Ll + lab[t]];
    for (int t = j + 1; t < Ss; t += 32)
        if (t < sl) gold += T[lab[t - 1] * Ll + lab[t]];
#pragma unroll
    for (int o = 16; o; o >>= 1) gold += __shfl_xor_sync(0xffffffffu, gold, o);

    float alpha = lg[j];
    for (int t = 1; t < Ss; t++) {
        float vmax = -1e30f;
#pragma unroll
        for (int i = 0; i < 32; i++) {
            float ai = __shfl_sync(0xffffffffu, alpha, i);
            vmax = fmaxf(vmax, ai + Tc[i]);
        }
        float s = 0.f;
#pragma unroll
        for (int i = 0; i < 32; i++) {
            float ai = __shfl_sync(0xffffffffu, alpha, i);
            s += expf(ai + Tc[i] - vmax);
        }
        float na = vmax + logf(s) + lg[(size_t)t * Ll + j];
        if (t < sl) alpha = na;
    }
    float m2 = alpha;
#pragma unroll
    for (int o = 16; o; o >>= 1) m2 = fmaxf(m2, __shfl_xor_sync(0xffffffffu, m2, o));
    float s2 = expf(alpha - m2);
#pragma unroll
    for (int o = 16; o; o >>= 1) s2 += __shfl_xor_sync(0xffffffffu, s2, o);
    if (j == 0) g_pb[b] = (m2 + logf(s2)) - gold;
}

__global__ void finalize_kernel(float* __restrict__ out)
{
    float s = 0.f;
#pragma unroll
    for (int i = 0; i < Bb; i++) s += g_pb[i];
    out[0] = s / (float)Bb;
}

// ---------------------------------------------------------------------------
// Launch
// ---------------------------------------------------------------------------
extern "C" void kernel_launch(void* const* d_in, const int* in_sizes, int n_in,
                              void* d_out, int out_size)
{
    const int* char_ids = (const int*)d_in[0];
    const int* kb_ids   = (const int*)d_in[1];
    const int* wbeg     = (const int*)d_in[2];
    const int* wlen     = (const int*)d_in[3];
    const int* label    = (const int*)d_in[4];
    const int* slen     = (const int*)d_in[5];
    const float* char_emb = (const float*)d_in[6];
    const float* kb_emb   = (const float*)d_in[7];
    const float* dense_W  = (const float*)d_in[8];
    const float* dense_b  = (const float*)d_in[9];
    const float* crf_T    = (const float*)d_in[10];

    const float* f_Wcx = (const float*)d_in[11];
    const float* f_Wch = (const float*)d_in[12];
    const float* f_bc  = (const float*)d_in[13];
    const float* f_Wwx = (const float*)d_in[14];
    const float* f_Wwh = (const float*)d_in[15];
    const float* f_bw  = (const float*)d_in[16];
    const float* f_Wlx = (const float*)d_in[17];
    const float* f_Wlc = (const float*)d_in[18];
    const float* f_bl  = (const float*)d_in[19];

    const float* r_Wcx = (const float*)d_in[20];
    const float* r_Wch = (const float*)d_in[21];
    const float* r_bc  = (const float*)d_in[22];
    const float* r_Wwx = (const float*)d_in[23];
    const float* r_Wwh = (const float*)d_in[24];
    const float* r_bw  = (const float*)d_in[25];
    const float* r_Wlx = (const float*)d_in[26];
    const float* r_Wlc = (const float*)d_in[27];
    const float* r_bl  = (const float*)d_in[28];

    prep_transpose_kernel<<<dim3(192, 4), 256>>>(f_Wwh, r_Wwh, f_Wlc, r_Wlc);

    char_gather_kernel<<<dim3(Bb, Ss / 8), 256>>>(char_emb, char_ids,
        f_Wcx, r_Wcx, f_Wlx, r_Wlx, f_bc, r_bc, f_bl, r_bl);
    kb_gather_kernel<<<dim3(Bb, Nn / 8), 256>>>(kb_emb, kb_ids,
        f_Wwx, r_Wwx, f_bw, r_bw);

    cudaFuncSetAttribute(lattice_kernel, cudaFuncAttributeMaxDynamicSharedMemorySize, SMEM_LAT);
    lattice_kernel<<<2 * Bb, NTHR, SMEM_LAT>>>(f_Wch, r_Wch, wbeg, wlen, slen);

    dense_kernel<<<(Bb * Ss) / 8, 256>>>(dense_W, dense_b);
    crf_kernel<<<Bb, 32>>>(label, slen, crf_T);
    finalize_kernel<<<1, 1>>>((float*)d_out);
}

// round 5
// speedup vs baseline: 1.0549x; 1.0549x over previous
#include <cuda_runtime.h>
#include <math.h>

#define Bb 16
#define Ss 128
#define Nn 64
#define Ee 128
#define Hh 128
#define Ll 32

// ---------------------------------------------------------------------------
// Device-global scratch (no runtime allocation allowed)
// ---------------------------------------------------------------------------
__device__ float g_Xg[(size_t)2 * Bb * Ss * 4 * Hh];   // (dir,b,t,512)
__device__ float g_Xl[(size_t)2 * Bb * Ss * Hh];       // (dir,b,t,128)
__device__ float g_Wg[(size_t)2 * Bb * Nn * 3 * Hh];   // (dir,b,n,384)
__device__ float g_WwhT[(size_t)2 * 3 * Hh * Hh];      // (dir,k(384),j(128)) transposed
__device__ float g_WlcT[(size_t)2 * Hh * Hh];          // (dir,k(128),j(128)) transposed
__device__ float g_feats[(size_t)Bb * Ss * 2 * Hh];    // (b,t,256)
__device__ float g_logits[(size_t)Bb * Ss * Ll];
__device__ float g_pb[Bb];

__device__ __forceinline__ float sigf(float x) { return 1.f / (1.f + expf(-x)); }

// --- f32x2 packed helpers (sm_103a) ---------------------------------------
__device__ __forceinline__ unsigned long long packf2(float lo, float hi) {
    unsigned long long r;
    asm("mov.b64 %0, {%1, %2};" : "=l"(r) : "f"(lo), "f"(hi));
    return r;
}
__device__ __forceinline__ void unpackf2(unsigned long long v, float& lo, float& hi) {
    asm("mov.b64 {%0, %1}, %2;" : "=f"(lo), "=f"(hi) : "l"(v));
}
__device__ __forceinline__ void ffma2(unsigned long long& acc,
                                      unsigned long long a, unsigned long long b) {
    asm("fma.rn.f32x2 %0, %1, %2, %0;" : "+l"(acc) : "l"(a), "l"(b));
}

// ---------------------------------------------------------------------------
// Prep: transpose Wwh (128x384 -> 384x128) and Wlc (128x128 -> T), both dirs
// ---------------------------------------------------------------------------
__global__ void prep_transpose_kernel(const float* __restrict__ fWwh,
                                      const float* __restrict__ rWwh,
                                      const float* __restrict__ fWlc,
                                      const float* __restrict__ rWlc)
{
    int which = blockIdx.y;
    const float* in;
    float* out;
    int K;
    if (which == 0)      { in = fWwh; out = g_WwhT;               K = 384; }
    else if (which == 1) { in = rWwh; out = g_WwhT + 384 * 128;   K = 384; }
    else if (which == 2) { in = fWlc; out = g_WlcT;               K = 128; }
    else                 { in = rWlc; out = g_WlcT + 128 * 128;   K = 128; }
    int idx = blockIdx.x * 256 + threadIdx.x;
    if (idx < K * 128) {
        int k = idx >> 7;
        int j = idx & 127;
        out[idx] = in[j * K + k];   // out[k*128+j]
    }
}

// ---------------------------------------------------------------------------
// Fused char-side gather GEMM (unchanged)
// ---------------------------------------------------------------------------
__global__ void __launch_bounds__(256) char_gather_kernel(
    const float* __restrict__ emb, const int* __restrict__ ids,
    const float* __restrict__ fWcx, const float* __restrict__ rWcx,
    const float* __restrict__ fWlx, const float* __restrict__ rWlx,
    const float* __restrict__ fbc, const float* __restrict__ rbc,
    const float* __restrict__ fbl, const float* __restrict__ rbl)
{
    __shared__ float xs[8][128];
    int b = blockIdx.x, r0 = blockIdx.y * 8, tid = threadIdx.x;

    for (int idx = tid; idx < 8 * 128; idx += 256) {
        int r = idx >> 7, e = idx & 127;
        int id = ids[b * Ss + r0 + r];
        xs[r][e] = emb[(size_t)id * 128 + e];
    }
    __syncthreads();

    const float* wp[5];
    float bias[5];
    float* op[5];
    int ostep[5];

    wp[0] = fWcx + tid;        bias[0] = fbc[tid];
    wp[1] = fWcx + tid + 256;  bias[1] = fbc[tid + 256];
    op[0] = g_Xg + ((size_t)b * Ss + r0) * 512 + tid;
    op[1] = op[0] + 256;
    ostep[0] = ostep[1] = 512;
    wp[2] = rWcx + tid;        bias[2] = rbc[tid];
    wp[3] = rWcx + tid + 256;  bias[3] = rbc[tid + 256];
    op[2] = g_Xg + ((size_t)(Bb + b) * Ss + (Ss - 1 - r0)) * 512 + tid;
    op[3] = op[2] + 256;
    ostep[2] = ostep[3] = -512;
    if (tid < 128) {
        wp[4] = fWlx + tid; bias[4] = fbl[tid];
        op[4] = g_Xl + ((size_t)b * Ss + r0) * 128 + tid;
        ostep[4] = 128;
    } else {
        int c = tid - 128;
        wp[4] = rWlx + c; bias[4] = rbl[c];
        op[4] = g_Xl + ((size_t)(Bb + b) * Ss + (Ss - 1 - r0)) * 128 + c;
        ostep[4] = -128;
    }

    float acc[8][5];
#pragma unroll
    for (int r = 0; r < 8; r++)
#pragma unroll
        for (int s = 0; s < 5; s++) acc[r][s] = 0.f;

    for (int e = 0; e < 128; e++) {
        float w0 = wp[0][(size_t)e * 512];
        float w1 = wp[1][(size_t)e * 512];
        float w2 = wp[2][(size_t)e * 512];
        float w3 = wp[3][(size_t)e * 512];
        float w4 = wp[4][(size_t)e * 128];
#pragma unroll
        for (int r = 0; r < 8; r++) {
            float x = xs[r][e];
            acc[r][0] = fmaf(x, w0, acc[r][0]);
            acc[r][1] = fmaf(x, w1, acc[r][1]);
            acc[r][2] = fmaf(x, w2, acc[r][2]);
            acc[r][3] = fmaf(x, w3, acc[r][3]);
            acc[r][4] = fmaf(x, w4, acc[r][4]);
        }
    }

#pragma unroll
    for (int r = 0; r < 8; r++)
#pragma unroll
        for (int s = 0; s < 5; s++)
            op[s][(long)r * ostep[s]] = acc[r][s] + bias[s];
}

// ---------------------------------------------------------------------------
// Fused kb-side gather GEMM (unchanged)
// ---------------------------------------------------------------------------
__global__ void __launch_bounds__(256) kb_gather_kernel(
    const float* __restrict__ emb, const int* __restrict__ ids,
    const float* __restrict__ fW, const float* __restrict__ rW,
    const float* __restrict__ fb, const float* __restrict__ rb)
{
    __shared__ float xs[8][128];
    int b = blockIdx.x, r0 = blockIdx.y * 8, tid = threadIdx.x;

    for (int idx = tid; idx < 8 * 128; idx += 256) {
        int r = idx >> 7, e = idx & 127;
        int id = ids[b * Nn + r0 + r];
        xs[r][e] = emb[(size_t)id * 128 + e];
    }
    __syncthreads();

    const float* wp[3];
    float bias[3];
    float* op[3];
#pragma unroll
    for (int s = 0; s < 3; s++) {
        int c = tid + 256 * s;
        if (c < 384) {
            wp[s] = fW + c; bias[s] = fb[c];
            op[s] = g_Wg + ((size_t)b * Nn + r0) * 384 + c;
        } else {
            int c2 = c - 384;
            wp[s] = rW + c2; bias[s] = rb[c2];
            op[s] = g_Wg + ((size_t)(Bb + b) * Nn + r0) * 384 + c2;
        }
    }

    float acc[8][3];
#pragma unroll
    for (int r = 0; r < 8; r++)
#pragma unroll
        for (int s = 0; s < 3; s++) acc[r][s] = 0.f;

    for (int e = 0; e < 128; e++) {
        float w0 = wp[0][(size_t)e * 384];
        float w1 = wp[1][(size_t)e * 384];
        float w2 = wp[2][(size_t)e * 384];
#pragma unroll
        for (int r = 0; r < 8; r++) {
            float x = xs[r][e];
            acc[r][0] = fmaf(x, w0, acc[r][0]);
            acc[r][1] = fmaf(x, w1, acc[r][1]);
            acc[r][2] = fmaf(x, w2, acc[r][2]);
        }
    }

#pragma unroll
    for (int r = 0; r < 8; r++)
#pragma unroll
        for (int s = 0; s < 3; s++)
            op[s][(size_t)r * 384] = acc[r][s] + bias[s];
}

// ---------------------------------------------------------------------------
// Lattice LSTM. One CTA per (dir,batch). 512 threads.
//  - Wch rows 0..63 in registers as 32 packed f32x2 lanes per thread.
//  - Wch rows 64..127 in smem packed 4-rows-per-quad -> 16 LDS.128/thread/step.
//  - Gate matvec uses fma.rn.f32x2 (64 FFMA2 instead of 128 FFMA).
//  - Xg software-pipelined (prefetch t+1 during step t).
//  - Only valid timestep window [t0,t1) executed; masked feats bulk-zeroed.
// ---------------------------------------------------------------------------
#define NTHR 512

// smem float offsets
#define OFF_W   0                      // 64 rows packed: 64*512 = 32768 floats
#define OFF_H   32768                  // 8*128
#define OFF_C   33792                  // 8*128
#define OFF_G   34816                  // 512
#define OFF_CW  35328                  // 128
#define OFF_SE  35456                  // 128
#define OFF_SC  35584                  // 128
#define FLT_END 35712
// ints: w_beg[64], w_end[64], wl_start[129], wl_idx[64], cur[128]
#define INT_CNT 449
#define SMEM_LAT (FLT_END * 4 + INT_CNT * 4)

__global__ void __launch_bounds__(NTHR, 1) lattice_kernel(
    const float* __restrict__ Wch_f, const float* __restrict__ Wch_r,
    const int* __restrict__ word_begin, const int* __restrict__ word_len,
    const int* __restrict__ seqlen)
{
    extern __shared__ float sm[];
    float* wsm      = sm + OFF_W;
    float* h_ring   = sm + OFF_H;
    float* c_ring   = sm + OFF_C;
    float* gates    = sm + OFF_G;
    float* cw       = sm + OFF_CW;
    float* sum_ew   = sm + OFF_SE;
    float* sum_ewcw = sm + OFF_SC;
    int* ip        = (int*)(sm + FLT_END);
    int* w_beg     = ip;
    int* w_end     = ip + 64;
    int* wl_start  = ip + 128;     // 129 entries
    int* wl_idx    = ip + 257;     // 64
    int* cur       = ip + 321;     // 128

    int dirb = blockIdx.x;
    int dir  = dirb / Bb;
    int b    = dirb - dir * Bb;
    int tid  = threadIdx.x;
    int sl   = seqlen[b];

    const float* Wch  = dir ? Wch_r : Wch_f;
    const float* WwhT = g_WwhT + (size_t)dir * 384 * 128;
    const float* WlcT = g_WlcT + (size_t)dir * 128 * 128;
    const float* Xg_b = g_Xg + (size_t)dirb * Ss * 512;
    const float* Xl_b = g_Xl + (size_t)dirb * Ss * 128;
    const float* Wg_b = g_Wg + (size_t)dirb * Nn * 384;

    // --- pack Wch rows 64..127 into smem, 4 rows per 16B quad per column ---
    for (int i = tid; i < 64 * 512; i += NTHR) {
        int r = i >> 9, c = i & 511;
        wsm[(((r >> 2) * 512 + c) << 2) + (r & 3)] = Wch[(size_t)(64 + r) * 512 + c];
    }

    // --- Wch rows 0..63 as 32 packed f32x2 register lanes (column tid) ---
    unsigned long long wregp[32];
#pragma unroll
    for (int r = 0; r < 32; r++)
        wregp[r] = packf2(Wch[(size_t)(2 * r) * 512 + tid],
                          Wch[(size_t)(2 * r + 1) * 512 + tid]);

    // valid window [t0, t1)
    int t0 = dir ? (Ss - sl) : 0;
    int t1 = dir ? Ss : sl;

    if (tid < Hh) {
        h_ring[(t0 & 7) * Hh + tid] = 0.f;
        c_ring[(t0 & 7) * Hh + tid] = 0.f;
    }

    // bulk-zero masked feats rows (original-time rows [sl, Ss), both dirs)
    for (int i = tid; i < (Ss - sl) * Hh; i += NTHR) {
        int row = sl + (i >> 7), col = i & 127;
        g_feats[((size_t)b * Ss + row) * (2 * Hh) + dir * Hh + col] = 0.f;
    }

    if (tid < Nn) {
        int bg = word_begin[b * Nn + tid];
        int ln = word_len[b * Nn + tid];
        int ef = min(bg + ln, Ss - 1);
        bool valid = ef < sl;
        if (dir == 0) {
            w_beg[tid] = bg;
            w_end[tid] = valid ? ef : -1;
        } else {
            w_beg[tid] = Ss - 1 - ef;
            w_end[tid] = valid ? (Ss - 1 - bg) : -1;
        }
    }
    __syncthreads();

    if (tid == 0) {
        for (int t = 0; t < Ss; t++) cur[t] = 0;
        for (int n = 0; n < Nn; n++) { int e = w_end[n]; if (e >= 0) cur[e]++; }
        wl_start[0] = 0;
        for (int t = 0; t < Ss; t++) wl_start[t + 1] = wl_start[t] + cur[t];
        for (int t = 0; t < Ss; t++) cur[t] = wl_start[t];
        for (int n = 0; n < Nn; n++) { int e = w_end[n]; if (e >= 0) wl_idx[cur[e]++] = n; }
    }
    __syncthreads();

    const ulonglong2* w4 = (const ulonglong2*)wsm;

    // software pipeline: Xg for step t prefetched at step t-1
    float xg = Xg_b[(size_t)t0 * 512 + tid];

    for (int t = t0; t < t1; t++) {
        int curS = (t & 7) * Hh;
        int nxtS = ((t + 1) & 7) * Hh;
        int wls = wl_start[t];
        int m = wl_start[t + 1] - wls;

        float xg_cur = xg;
        if (t + 1 < t1) xg = Xg_b[(size_t)(t + 1) * 512 + tid];   // prefetch

        // ---- char gate matvec, f32x2 packed ----
        {
            const ulonglong2* hh = (const ulonglong2*)(h_ring + curS);  // 32 quads
            unsigned long long accA = packf2(xg_cur, 0.f);
            unsigned long long accB = packf2(0.f, 0.f);
#pragma unroll
            for (int k = 0; k < 16; k++) {
                ulonglong2 hq = hh[k];            // h rows 4k..4k+3
                ffma2(accA, hq.x, wregp[2 * k]);
                ffma2(accB, hq.y, wregp[2 * k + 1]);
            }
#pragma unroll
            for (int i = 0; i < 16; i++) {
                ulonglong2 hq = hh[16 + i];       // h rows 64+4i..64+4i+3
                ulonglong2 wq = w4[i * 512 + tid];
                ffma2(accA, hq.x, wq.x);
                ffma2(accB, hq.y, wq.y);
            }
            float a0, a1, b0, b1;
            unpackf2(accA, a0, a1);
            unpackf2(accB, b0, b1);
            gates[tid] = (a0 + a1) + (b0 + b1);
        }

        // ---- word lattice contributions (threads 0-127) ----
        if (m > 0) {
            if (tid < Hh) { sum_ew[tid] = 0.f; sum_ewcw[tid] = 0.f; }
            for (int wv = 0; wv < m; wv++) {
                int n   = wl_idx[wls + wv];
                int bgS = (w_beg[n] & 7) * Hh;
                if (tid < Hh) {
                    const float4* hb4 = (const float4*)(h_ring + bgS);
                    const float4* p0  = (const float4*)(WwhT + (size_t)tid * 128);
                    const float4* p1  = (const float4*)(WwhT + (size_t)(tid + 128) * 128);
                    const float4* p2  = (const float4*)(WwhT + (size_t)(tid + 256) * 128);
                    float acc0 = Wg_b[(size_t)n * 384 + tid];
                    float acc1 = Wg_b[(size_t)n * 384 + tid + 128];
                    float acc2 = Wg_b[(size_t)n * 384 + tid + 256];
#pragma unroll 2
                    for (int j = 0; j < 32; j++) {
                        float4 hv = hb4[j];
                        float4 x0 = p0[j], x1 = p1[j], x2 = p2[j];
                        acc0 = fmaf(hv.x, x0.x, acc0);
                        acc0 = fmaf(hv.y, x0.y, acc0);
                        acc0 = fmaf(hv.z, x0.z, acc0);
                        acc0 = fmaf(hv.w, x0.w, acc0);
                        acc1 = fmaf(hv.x, x1.x, acc1);
                        acc1 = fmaf(hv.y, x1.y, acc1);
                        acc1 = fmaf(hv.z, x1.z, acc1);
                        acc1 = fmaf(hv.w, x1.w, acc1);
                        acc2 = fmaf(hv.x, x2.x, acc2);
                        acc2 = fmaf(hv.y, x2.y, acc2);
                        acc2 = fmaf(hv.z, x2.z, acc2);
                        acc2 = fmaf(hv.w, x2.w, acc2);
                    }
                    cw[tid] = sigf(acc1) * c_ring[bgS + tid] + sigf(acc0) * tanhf(acc2);
                }
                __syncthreads();   // cw visible (also orders gates for update)
                if (tid < Hh) {
                    const float4* c4  = (const float4*)cw;
                    const float4* wl4 = (const float4*)(WlcT + (size_t)tid * 128);
                    float q0 = 0.f, q1 = 0.f;
#pragma unroll 2
                    for (int j = 0; j < 32; j += 2) {
                        float4 cv0 = c4[j],     y0 = wl4[j];
                        float4 cv1 = c4[j + 1], y1 = wl4[j + 1];
                        q0 = fmaf(cv0.x, y0.x, q0);
                        q0 = fmaf(cv0.y, y0.y, q0);
                        q0 = fmaf(cv0.z, y0.z, q0);
                        q0 = fmaf(cv0.w, y0.w, q0);
                        q1 = fmaf(cv1.x, y1.x, q1);
                        q1 = fmaf(cv1.y, y1.y, q1);
                        q1 = fmaf(cv1.z, y1.z, q1);
                        q1 = fmaf(cv1.w, y1.w, q1);
                    }
                    float ew = expf(sigf(Xl_b[(size_t)t * 128 + tid] + q0 + q1));
                    sum_ew[tid]   += ew;
                    sum_ewcw[tid] += ew * cw[tid];
                }
                __syncthreads();   // cw reusable / sums visible at loop end
            }
        } else {
            __syncthreads();       // gates visible for update
        }

        // ---- cell/state update (threads 0-127) ----
        if (tid < Hh) {
            float ig = sigf(gates[tid]);
            float fg = sigf(gates[Hh + tid]);
            float og = sigf(gates[2 * Hh + tid]);
            float gg = tanhf(gates[3 * Hh + tid]);
            float cp = c_ring[curS + tid];
            float ct;
            if (m > 0) {
                float ec = expf(ig);
                ct = (ec * gg + sum_ewcw[tid]) / (ec + sum_ew[tid]);
            } else {
                ct = fg * cp + ig * gg;
            }
            float ht = og * tanhf(ct);
            h_ring[nxtS + tid] = ht;
            c_ring[nxtS + tid] = ct;
            int tt = (dir == 0) ? t : (Ss - 1 - t);
            g_feats[((size_t)b * Ss + tt) * (2 * Hh) + dir * Hh + tid] = ht;
        }
        __syncthreads();   // new state visible for next step
    }
}

// ---------------------------------------------------------------------------
// Dense projection
// ---------------------------------------------------------------------------
__global__ void dense_kernel(const float* __restrict__ W, const float* __restrict__ bias)
{
    __shared__ float fs[8][2 * Hh];
    int row0 = blockIdx.x * 8;
    int tid = threadIdx.x;
    for (int idx = tid; idx < 8 * 2 * Hh; idx += 256) {
        int r = idx >> 8;
        int e = idx & 255;
        fs[r][e] = g_feats[(size_t)(row0 + r) * (2 * Hh) + e];
    }
    __syncthreads();
    int r = tid >> 5;
    int col = tid & 31;
    float acc = bias[col];
#pragma unroll 8
    for (int e = 0; e < 2 * Hh; e++) acc = fmaf(fs[r][e], W[e * Ll + col], acc);
    g_logits[(size_t)(row0 + r) * Ll + col] = acc;
}

// ---------------------------------------------------------------------------
// CRF
// ---------------------------------------------------------------------------
__global__ void crf_kernel(const int* __restrict__ label,
                           const int* __restrict__ seqlen,
                           const float* __restrict__ T)
{
    int b = blockIdx.x;
    int j = threadIdx.x;
    int sl = seqlen[b];
    const float* lg = g_logits + (size_t)b * Ss * Ll;
    const int*   lab = label + b * Ss;

    float Tc[32];
#pragma unroll
    for (int i = 0; i < 32; i++) Tc[i] = T[i * Ll + j];

    float gold = 0.f;
    for (int t = j; t < Ss; t += 32)
        if (t < sl) gold += lg[t * Ll + lab[t]];
    for (int t = j + 1; t < Ss; t += 32)
        if (t < sl) gold += T[lab[t - 1] * Ll + lab[t]];
#pragma unroll
    for (int o = 16; o; o >>= 1) gold += __shfl_xor_sync(0xffffffffu, gold, o);

    float alpha = lg[j];
    for (int t = 1; t < Ss; t++) {
        float vmax = -1e30f;
#pragma unroll
        for (int i = 0; i < 32; i++) {
            float ai = __shfl_sync(0xffffffffu, alpha, i);
            vmax = fmaxf(vmax, ai + Tc[i]);
        }
        float s = 0.f;
#pragma unroll
        for (int i = 0; i < 32; i++) {
            float ai = __shfl_sync(0xffffffffu, alpha, i);
            s += expf(ai + Tc[i] - vmax);
        }
        float na = vmax + logf(s) + lg[(size_t)t * Ll + j];
        if (t < sl) alpha = na;
    }
    float m2 = alpha;
#pragma unroll
    for (int o = 16; o; o >>= 1) m2 = fmaxf(m2, __shfl_xor_sync(0xffffffffu, m2, o));
    float s2 = expf(alpha - m2);
#pragma unroll
    for (int o = 16; o; o >>= 1) s2 += __shfl_xor_sync(0xffffffffu, s2, o);
    if (j == 0) g_pb[b] = (m2 + logf(s2)) - gold;
}

__global__ void finalize_kernel(float* __restrict__ out)
{
    float s = 0.f;
#pragma unroll
    for (int i = 0; i < Bb; i++) s += g_pb[i];
    out[0] = s / (float)Bb;
}

// ---------------------------------------------------------------------------
// Launch
// ---------------------------------------------------------------------------
extern "C" void kernel_launch(void* const* d_in, const int* in_sizes, int n_in,
                              void* d_out, int out_size)
{
    const int* char_ids = (const int*)d_in[0];
    const int* kb_ids   = (const int*)d_in[1];
    const int* wbeg     = (const int*)d_in[2];
    const int* wlen     = (const int*)d_in[3];
    const int* label    = (const int*)d_in[4];
    const int* slen     = (const int*)d_in[5];
    const float* char_emb = (const float*)d_in[6];
    const float* kb_emb   = (const float*)d_in[7];
    const float* dense_W  = (const float*)d_in[8];
    const float* dense_b  = (const float*)d_in[9];
    const float* crf_T    = (const float*)d_in[10];

    const float* f_Wcx = (const float*)d_in[11];
    const float* f_Wch = (const float*)d_in[12];
    const float* f_bc  = (const float*)d_in[13];
    const float* f_Wwx = (const float*)d_in[14];
    const float* f_Wwh = (const float*)d_in[15];
    const float* f_bw  = (const float*)d_in[16];
    const float* f_Wlx = (const float*)d_in[17];
    const float* f_Wlc = (const float*)d_in[18];
    const float* f_bl  = (const float*)d_in[19];

    const float* r_Wcx = (const float*)d_in[20];
    const float* r_Wch = (const float*)d_in[21];
    const float* r_bc  = (const float*)d_in[22];
    const float* r_Wwx = (const float*)d_in[23];
    const float* r_Wwh = (const float*)d_in[24];
    const float* r_bw  = (const float*)d_in[25];
    const float* r_Wlx = (const float*)d_in[26];
    const float* r_Wlc = (const float*)d_in[27];
    const float* r_bl  = (const float*)d_in[28];

    prep_transpose_kernel<<<dim3(192, 4), 256>>>(f_Wwh, r_Wwh, f_Wlc, r_Wlc);

    char_gather_kernel<<<dim3(Bb, Ss / 8), 256>>>(char_emb, char_ids,
        f_Wcx, r_Wcx, f_Wlx, r_Wlx, f_bc, r_bc, f_bl, r_bl);
    kb_gather_kernel<<<dim3(Bb, Nn / 8), 256>>>(kb_emb, kb_ids,
        f_Wwx, r_Wwx, f_bw, r_bw);

    cudaFuncSetAttribute(lattice_kernel, cudaFuncAttributeMaxDynamicSharedMemorySize, SMEM_LAT);
    lattice_kernel<<<2 * Bb, NTHR, SMEM_LAT>>>(f_Wch, r_Wch, wbeg, wlen, slen);

    dense_kernel<<<(Bb * Ss) / 8, 256>>>(dense_W, dense_b);
    crf_kernel<<<Bb, 32>>>(label, slen, crf_T);
    finalize_kernel<<<1, 1>>>((float*)d_out);
}

// round 6
// speedup vs baseline: 1.4286x; 1.3542x over previous
#include <cuda_runtime.h>
#include <math.h>

#define Bb 16
#define Ss 128
#define Nn 64
#define Ee 128
#define Hh 128
#define Ll 32

// ---------------------------------------------------------------------------
// Device-global scratch
// ---------------------------------------------------------------------------
__device__ float g_Xg[(size_t)2 * Bb * Ss * 4 * Hh];   // (dir,b,t,512)
__device__ float g_Xl[(size_t)2 * Bb * Ss * Hh];       // (dir,b,t,128)
__device__ float g_Wg[(size_t)2 * Bb * Nn * 3 * Hh];   // (dir,b,n,384)
__device__ float g_Wwh4[(size_t)2 * 128 * 384];        // quad-interleaved (dir, j4, k, e)
__device__ float g_Wlc4[(size_t)2 * 128 * 128];        // quad-interleaved (dir, j4, k, e)
__device__ float g_feats[(size_t)Bb * Ss * 2 * Hh];
__device__ float g_logits[(size_t)Bb * Ss * Ll];
__device__ float g_pb[Bb];

// fast transcendentals (~2 ulp; tolerance is 1e-3)
__device__ __forceinline__ float sigf(float x) {
    return __fdividef(1.f, 1.f + __expf(-x));
}
__device__ __forceinline__ float tanhfast(float x) {
    return 1.f - 2.f * __fdividef(1.f, __expf(2.f * x) + 1.f);
}

// --- f32x2 packed helpers (sm_103a) ---------------------------------------
__device__ __forceinline__ unsigned long long packf2(float lo, float hi) {
    unsigned long long r;
    asm("mov.b64 %0, {%1, %2};" : "=l"(r) : "f"(lo), "f"(hi));
    return r;
}
__device__ __forceinline__ void unpackf2(unsigned long long v, float& lo, float& hi) {
    asm("mov.b64 {%0, %1}, %2;" : "=f"(lo), "=f"(hi) : "l"(v));
}
__device__ __forceinline__ void ffma2(unsigned long long& acc,
                                      unsigned long long a, unsigned long long b) {
    asm("fma.rn.f32x2 %0, %1, %2, %0;" : "+l"(acc) : "l"(a), "l"(b));
}

// ---------------------------------------------------------------------------
// Prep: pack Wwh/Wlc into quad-interleaved layouts (coalesced/conflict-free)
//   W4[(j4*K + k)*4 + e] = W[(4*j4+e)*K + k]
// ---------------------------------------------------------------------------
__global__ void prep_pack_kernel(const float* __restrict__ fWwh,
                                 const float* __restrict__ rWwh,
                                 const float* __restrict__ fWlc,
                                 const float* __restrict__ rWlc)
{
    int which = blockIdx.y;
    int idx = blockIdx.x * 256 + threadIdx.x;
    if (which < 2) {
        const float* in = which ? rWwh : fWwh;
        float* out = g_Wwh4 + (size_t)which * 128 * 384;
        if (idx < 128 * 384) {
            int k = idx % 384, j = idx / 384;
            out[((size_t)(j >> 2) * 384 + k) * 4 + (j & 3)] = in[(size_t)j * 384 + k];
        }
    } else {
        const float* in = (which == 3) ? rWlc : fWlc;
        float* out = g_Wlc4 + (size_t)(which - 2) * 128 * 128;
        if (idx < 128 * 128) {
            int k = idx & 127, j = idx >> 7;
            out[((size_t)(j >> 2) * 128 + k) * 4 + (j & 3)] = in[(size_t)j * 128 + k];
        }
    }
}

// ---------------------------------------------------------------------------
// Fused char-side gather GEMM (unchanged)
// ---------------------------------------------------------------------------
__global__ void __launch_bounds__(256) char_gather_kernel(
    const float* __restrict__ emb, const int* __restrict__ ids,
    const float* __restrict__ fWcx, const float* __restrict__ rWcx,
    const float* __restrict__ fWlx, const float* __restrict__ rWlx,
    const float* __restrict__ fbc, const float* __restrict__ rbc,
    const float* __restrict__ fbl, const float* __restrict__ rbl)
{
    __shared__ float xs[8][128];
    int b = blockIdx.x, r0 = blockIdx.y * 8, tid = threadIdx.x;

    for (int idx = tid; idx < 8 * 128; idx += 256) {
        int r = idx >> 7, e = idx & 127;
        int id = ids[b * Ss + r0 + r];
        xs[r][e] = emb[(size_t)id * 128 + e];
    }
    __syncthreads();

    const float* wp[5];
    float bias[5];
    float* op[5];
    int ostep[5];

    wp[0] = fWcx + tid;        bias[0] = fbc[tid];
    wp[1] = fWcx + tid + 256;  bias[1] = fbc[tid + 256];
    op[0] = g_Xg + ((size_t)b * Ss + r0) * 512 + tid;
    op[1] = op[0] + 256;
    ostep[0] = ostep[1] = 512;
    wp[2] = rWcx + tid;        bias[2] = rbc[tid];
    wp[3] = rWcx + tid + 256;  bias[3] = rbc[tid + 256];
    op[2] = g_Xg + ((size_t)(Bb + b) * Ss + (Ss - 1 - r0)) * 512 + tid;
    op[3] = op[2] + 256;
    ostep[2] = ostep[3] = -512;
    if (tid < 128) {
        wp[4] = fWlx + tid; bias[4] = fbl[tid];
        op[4] = g_Xl + ((size_t)b * Ss + r0) * 128 + tid;
        ostep[4] = 128;
    } else {
        int c = tid - 128;
        wp[4] = rWlx + c; bias[4] = rbl[c];
        op[4] = g_Xl + ((size_t)(Bb + b) * Ss + (Ss - 1 - r0)) * 128 + c;
        ostep[4] = -128;
    }

    float acc[8][5];
#pragma unroll
    for (int r = 0; r < 8; r++)
#pragma unroll
        for (int s = 0; s < 5; s++) acc[r][s] = 0.f;

    for (int e = 0; e < 128; e++) {
        float w0 = wp[0][(size_t)e * 512];
        float w1 = wp[1][(size_t)e * 512];
        float w2 = wp[2][(size_t)e * 512];
        float w3 = wp[3][(size_t)e * 512];
        float w4 = wp[4][(size_t)e * 128];
#pragma unroll
        for (int r = 0; r < 8; r++) {
            float x = xs[r][e];
            acc[r][0] = fmaf(x, w0, acc[r][0]);
            acc[r][1] = fmaf(x, w1, acc[r][1]);
            acc[r][2] = fmaf(x, w2, acc[r][2]);
            acc[r][3] = fmaf(x, w3, acc[r][3]);
            acc[r][4] = fmaf(x, w4, acc[r][4]);
        }
    }

#pragma unroll
    for (int r = 0; r < 8; r++)
#pragma unroll
        for (int s = 0; s < 5; s++)
            op[s][(long)r * ostep[s]] = acc[r][s] + bias[s];
}

// ---------------------------------------------------------------------------
// Fused kb-side gather GEMM (unchanged)
// ---------------------------------------------------------------------------
__global__ void __launch_bounds__(256) kb_gather_kernel(
    const float* __restrict__ emb, const int* __restrict__ ids,
    const float* __restrict__ fW, const float* __restrict__ rW,
    const float* __restrict__ fb, const float* __restrict__ rb)
{
    __shared__ float xs[8][128];
    int b = blockIdx.x, r0 = blockIdx.y * 8, tid = threadIdx.x;

    for (int idx = tid; idx < 8 * 128; idx += 256) {
        int r = idx >> 7, e = idx & 127;
        int id = ids[b * Nn + r0 + r];
        xs[r][e] = emb[(size_t)id * 128 + e];
    }
    __syncthreads();

    const float* wp[3];
    float bias[3];
    float* op[3];
#pragma unroll
    for (int s = 0; s < 3; s++) {
        int c = tid + 256 * s;
        if (c < 384) {
            wp[s] = fW + c; bias[s] = fb[c];
            op[s] = g_Wg + ((size_t)b * Nn + r0) * 384 + c;
        } else {
            int c2 = c - 384;
            wp[s] = rW + c2; bias[s] = rb[c2];
            op[s] = g_Wg + ((size_t)(Bb + b) * Nn + r0) * 384 + c2;
        }
    }

    float acc[8][3];
#pragma unroll
    for (int r = 0; r < 8; r++)
#pragma unroll
        for (int s = 0; s < 3; s++) acc[r][s] = 0.f;

    for (int e = 0; e < 128; e++) {
        float w0 = wp[0][(size_t)e * 384];
        float w1 = wp[1][(size_t)e * 384];
        float w2 = wp[2][(size_t)e * 384];
#pragma unroll
        for (int r = 0; r < 8; r++) {
            float x = xs[r][e];
            acc[r][0] = fmaf(x, w0, acc[r][0]);
            acc[r][1] = fmaf(x, w1, acc[r][1]);
            acc[r][2] = fmaf(x, w2, acc[r][2]);
        }
    }

#pragma unroll
    for (int r = 0; r < 8; r++)
#pragma unroll
        for (int s = 0; s < 3; s++)
            op[s][(size_t)r * 384] = acc[r][s] + bias[s];
}

// ---------------------------------------------------------------------------
// Lattice LSTM: 640 threads/CTA.
//   threads 0-511  : char-gate matvec (f32x2, 64 reg rows + 64 smem quad rows)
//   threads 512-639: word path (coalesced Wwh4 global, Wlc4 in smem) + update
// Word path runs CONCURRENTLY with the char matvec each step.
// ---------------------------------------------------------------------------
#define NTHR 640

// smem float offsets
#define OFF_W    0                     // 64*512 = 32768
#define OFF_WLC  32768                 // 128*128 = 16384
#define OFF_H    49152                 // 8*128
#define OFF_C    50176                 // 8*128
#define OFF_G    51200                 // 512
#define OFF_CW   51712                 // 128
#define OFF_SE   51840                 // 128
#define OFF_SC   51968                 // 128
#define FLT_END  52096
#define INT_CNT  449
#define SMEM_LAT (FLT_END * 4 + INT_CNT * 4)

__global__ void __launch_bounds__(NTHR, 1) lattice_kernel(
    const float* __restrict__ Wch_f, const float* __restrict__ Wch_r,
    const int* __restrict__ word_begin, const int* __restrict__ word_len,
    const int* __restrict__ seqlen)
{
    extern __shared__ float sm[];
    float* wsm      = sm + OFF_W;
    float* wlcs     = sm + OFF_WLC;
    float* h_ring   = sm + OFF_H;
    float* c_ring   = sm + OFF_C;
    float* gates    = sm + OFF_G;
    float* cw       = sm + OFF_CW;
    float* sum_ew   = sm + OFF_SE;
    float* sum_ewcw = sm + OFF_SC;
    int* ip        = (int*)(sm + FLT_END);
    int* w_beg     = ip;
    int* w_end     = ip + 64;
    int* wl_start  = ip + 128;
    int* wl_idx    = ip + 257;
    int* cur       = ip + 321;

    int dirb = blockIdx.x;
    int dir  = dirb / Bb;
    int b    = dirb - dir * Bb;
    int tid  = threadIdx.x;
    int sl   = seqlen[b];

    const float* Wch  = dir ? Wch_r : Wch_f;
    const float* Wwh4 = g_Wwh4 + (size_t)dir * 128 * 384;
    const float* Xg_b = g_Xg + (size_t)dirb * Ss * 512;
    const float* Xl_b = g_Xl + (size_t)dirb * Ss * 128;
    const float* Wg_b = g_Wg + (size_t)dirb * Nn * 384;

    // load smem: Wch rows 64..127 packed 4-rows-per-quad; Wlc4 copied contig
    for (int i = tid; i < 64 * 512; i += NTHR) {
        int r = i >> 9, c = i & 511;
        wsm[(((r >> 2) * 512 + c) << 2) + (r & 3)] = Wch[(size_t)(64 + r) * 512 + c];
    }
    {
        const float* src = g_Wlc4 + (size_t)dir * 128 * 128;
        for (int i = tid; i < 128 * 128; i += NTHR) wlcs[i] = src[i];
    }

    // Wch rows 0..63 as 32 packed f32x2 lanes (char threads only)
    unsigned long long wregp[32];
    if (tid < 512) {
#pragma unroll
        for (int r = 0; r < 32; r++)
            wregp[r] = packf2(Wch[(size_t)(2 * r) * 512 + tid],
                              Wch[(size_t)(2 * r + 1) * 512 + tid]);
    }

    int t0 = dir ? (Ss - sl) : 0;
    int t1 = dir ? Ss : sl;

    if (tid >= 512) {
        int k = tid - 512;
        h_ring[(t0 & 7) * Hh + k] = 0.f;
        c_ring[(t0 & 7) * Hh + k] = 0.f;
    }

    // zero masked feats rows
    for (int i = tid; i < (Ss - sl) * Hh; i += NTHR) {
        int row = sl + (i >> 7), col = i & 127;
        g_feats[((size_t)b * Ss + row) * (2 * Hh) + dir * Hh + col] = 0.f;
    }

    if (tid < Nn) {
        int bg = word_begin[b * Nn + tid];
        int ln = word_len[b * Nn + tid];
        int ef = min(bg + ln, Ss - 1);
        bool valid = ef < sl;
        if (dir == 0) {
            w_beg[tid] = bg;
            w_end[tid] = valid ? ef : -1;
        } else {
            w_beg[tid] = Ss - 1 - ef;
            w_end[tid] = valid ? (Ss - 1 - bg) : -1;
        }
    }
    __syncthreads();

    if (tid == 0) {
        for (int t = 0; t < Ss; t++) cur[t] = 0;
        for (int n = 0; n < Nn; n++) { int e = w_end[n]; if (e >= 0) cur[e]++; }
        wl_start[0] = 0;
        for (int t = 0; t < Ss; t++) wl_start[t + 1] = wl_start[t] + cur[t];
        for (int t = 0; t < Ss; t++) cur[t] = wl_start[t];
        for (int n = 0; n < Nn; n++) { int e = w_end[n]; if (e >= 0) wl_idx[cur[e]++] = n; }
    }
    __syncthreads();

    const ulonglong2* w4 = (const ulonglong2*)wsm;
    const float4* wlc4 = (const float4*)wlcs;
    const float4* Ww4  = (const float4*)Wwh4;

    float xg = (tid < 512) ? Xg_b[(size_t)t0 * 512 + tid] : 0.f;

    for (int t = t0; t < t1; t++) {
        int curS = (t & 7) * Hh;
        int nxtS = ((t + 1) & 7) * Hh;
        int wls = wl_start[t];
        int m = wl_start[t + 1] - wls;

        if (tid < 512) {
            // ---- char gate matvec (f32x2) ----
            float xg_cur = xg;
            if (t + 1 < t1) xg = Xg_b[(size_t)(t + 1) * 512 + tid];

            const ulonglong2* hh = (const ulonglong2*)(h_ring + curS);
            unsigned long long accA = packf2(xg_cur, 0.f);
            unsigned long long accB = packf2(0.f, 0.f);
#pragma unroll
            for (int k = 0; k < 16; k++) {
                ulonglong2 hq = hh[k];
                ffma2(accA, hq.x, wregp[2 * k]);
                ffma2(accB, hq.y, wregp[2 * k + 1]);
            }
#pragma unroll
            for (int i = 0; i < 16; i++) {
                ulonglong2 hq = hh[16 + i];
                ulonglong2 wq = w4[i * 512 + tid];
                ffma2(accA, hq.x, wq.x);
                ffma2(accB, hq.y, wq.y);
            }
            float a0, a1, b0, b1;
            unpackf2(accA, a0, a1);
            unpackf2(accB, b0, b1);
            gates[tid] = (a0 + a1) + (b0 + b1);
        } else {
            // ---- word path (concurrent with char matvec) ----
            int wt = tid - 512;
            if (m > 0) {
                float sew = 0.f, sewc = 0.f;
                for (int wv = 0; wv < m; wv++) {
                    int n   = wl_idx[wls + wv];
                    int bgS = (w_beg[n] & 7) * Hh;
                    float xl = __ldg(Xl_b + (size_t)t * 128 + wt);
                    const float4* hb4 = (const float4*)(h_ring + bgS);
                    float acc0 = __ldg(Wg_b + (size_t)n * 384 + wt);
                    float acc1 = __ldg(Wg_b + (size_t)n * 384 + wt + 128);
                    float acc2 = __ldg(Wg_b + (size_t)n * 384 + wt + 256);
#pragma unroll 8
                    for (int j = 0; j < 32; j++) {
                        float4 hv = hb4[j];
                        float4 v0 = __ldg(Ww4 + (size_t)j * 384 + wt);
                        float4 v1 = __ldg(Ww4 + (size_t)j * 384 + wt + 128);
                        float4 v2 = __ldg(Ww4 + (size_t)j * 384 + wt + 256);
                        acc0 = fmaf(hv.x, v0.x, acc0);
                        acc0 = fmaf(hv.y, v0.y, acc0);
                        acc0 = fmaf(hv.z, v0.z, acc0);
                        acc0 = fmaf(hv.w, v0.w, acc0);
                        acc1 = fmaf(hv.x, v1.x, acc1);
                        acc1 = fmaf(hv.y, v1.y, acc1);
                        acc1 = fmaf(hv.z, v1.z, acc1);
                        acc1 = fmaf(hv.w, v1.w, acc1);
                        acc2 = fmaf(hv.x, v2.x, acc2);
                        acc2 = fmaf(hv.y, v2.y, acc2);
                        acc2 = fmaf(hv.z, v2.z, acc2);
                        acc2 = fmaf(hv.w, v2.w, acc2);
                    }
                    float cwv = sigf(acc1) * c_ring[bgS + wt] + sigf(acc0) * tanhfast(acc2);
                    cw[wt] = cwv;
                    asm volatile("bar.sync 1, 128;" ::: "memory");
                    const float4* c4 = (const float4*)cw;
                    float q0 = 0.f, q1 = 0.f;
#pragma unroll 8
                    for (int j = 0; j < 32; j += 2) {
                        float4 cv0 = c4[j],     y0 = wlc4[j * 128 + wt];
                        float4 cv1 = c4[j + 1], y1 = wlc4[(j + 1) * 128 + wt];
                        q0 = fmaf(cv0.x, y0.x, q0);
                        q0 = fmaf(cv0.y, y0.y, q0);
                        q0 = fmaf(cv0.z, y0.z, q0);
                        q0 = fmaf(cv0.w, y0.w, q0);
                        q1 = fmaf(cv1.x, y1.x, q1);
                        q1 = fmaf(cv1.y, y1.y, q1);
                        q1 = fmaf(cv1.z, y1.z, q1);
                        q1 = fmaf(cv1.w, y1.w, q1);
                    }
                    float ew = __expf(sigf(xl + q0 + q1));
                    sew  += ew;
                    sewc += ew * cwv;
                    asm volatile("bar.sync 1, 128;" ::: "memory");
                }
                sum_ew[wt] = sew;
                sum_ewcw[wt] = sewc;
            }
        }
        __syncthreads();   // [A] gates + word sums ready

        if (tid >= 512) {
            int k = tid - 512;
            float ig = sigf(gates[k]);
            float fg = sigf(gates[Hh + k]);
            float og = sigf(gates[2 * Hh + k]);
            float gg = tanhfast(gates[3 * Hh + k]);
            float cp = c_ring[curS + k];
            float ct;
            if (m > 0) {
                float ec = __expf(ig);
                ct = __fdividef(ec * gg + sum_ewcw[k], ec + sum_ew[k]);
            } else {
                ct = fg * cp + ig * gg;
            }
            float ht = og * tanhfast(ct);
            h_ring[nxtS + k] = ht;
            c_ring[nxtS + k] = ct;
            int tt = (dir == 0) ? t : (Ss - 1 - t);
            g_feats[((size_t)b * Ss + tt) * (2 * Hh) + dir * Hh + k] = ht;
        }
        __syncthreads();   // [B] new state visible
    }
}

// ---------------------------------------------------------------------------
// Dense projection
// ---------------------------------------------------------------------------
__global__ void dense_kernel(const float* __restrict__ W, const float* __restrict__ bias)
{
    __shared__ float fs[8][2 * Hh];
    int row0 = blockIdx.x * 8;
    int tid = threadIdx.x;
    for (int idx = tid; idx < 8 * 2 * Hh; idx += 256) {
        int r = idx >> 8;
        int e = idx & 255;
        fs[r][e] = g_feats[(size_t)(row0 + r) * (2 * Hh) + e];
    }
    __syncthreads();
    int r = tid >> 5;
    int col = tid & 31;
    float acc = bias[col];
#pragma unroll 8
    for (int e = 0; e < 2 * Hh; e++) acc = fmaf(fs[r][e], W[e * Ll + col], acc);
    g_logits[(size_t)(row0 + r) * Ll + col] = acc;
}

// ---------------------------------------------------------------------------
// CRF (precise expf/logf kept here)
// ---------------------------------------------------------------------------
__global__ void crf_kernel(const int* __restrict__ label,
                           const int* __restrict__ seqlen,
                           const float* __restrict__ T)
{
    int b = blockIdx.x;
    int j = threadIdx.x;
    int sl = seqlen[b];
    const float* lg = g_logits + (size_t)b * Ss * Ll;
    const int*   lab = label + b * Ss;

    float Tc[32];
#pragma unroll
    for (int i = 0; i < 32; i++) Tc[i] = T[i * Ll + j];

    float gold = 0.f;
    for (int t = j; t < Ss; t += 32)
        if (t < sl) gold += lg[t * Ll + lab[t]];
    for (int t = j + 1; t < Ss; t += 32)
        if (t < sl) gold += T[lab[t - 1] * Ll + lab[t]];
#pragma unroll
    for (int o = 16; o; o >>= 1) gold += __shfl_xor_sync(0xffffffffu, gold, o);

    float alpha = lg[j];
    for (int t = 1; t < Ss; t++) {
        float vmax = -1e30f;
#pragma unroll
        for (int i = 0; i < 32; i++) {
            float ai = __shfl_sync(0xffffffffu, alpha, i);
            vmax = fmaxf(vmax, ai + Tc[i]);
        }
        float s = 0.f;
#pragma unroll
        for (int i = 0; i < 32; i++) {
            float ai = __shfl_sync(0xffffffffu, alpha, i);
            s += expf(ai + Tc[i] - vmax);
        }
        float na = vmax + logf(s) + lg[(size_t)t * Ll + j];
        if (t < sl) alpha = na;
    }
    float m2 = alpha;
#pragma unroll
    for (int o = 16; o; o >>= 1) m2 = fmaxf(m2, __shfl_xor_sync(0xffffffffu, m2, o));
    float s2 = expf(alpha - m2);
#pragma unroll
    for (int o = 16; o; o >>= 1) s2 += __shfl_xor_sync(0xffffffffu, s2, o);
    if (j == 0) g_pb[b] = (m2 + logf(s2)) - gold;
}

__global__ void finalize_kernel(float* __restrict__ out)
{
    float s = 0.f;
#pragma unroll
    for (int i = 0; i < Bb; i++) s += g_pb[i];
    out[0] = s / (float)Bb;
}

// ---------------------------------------------------------------------------
// Launch
// ---------------------------------------------------------------------------
extern "C" void kernel_launch(void* const* d_in, const int* in_sizes, int n_in,
                              void* d_out, int out_size)
{
    const int* char_ids = (const int*)d_in[0];
    const int* kb_ids   = (const int*)d_in[1];
    const int* wbeg     = (const int*)d_in[2];
    const int* wlen     = (const int*)d_in[3];
    const int* label    = (const int*)d_in[4];
    const int* slen     = (const int*)d_in[5];
    const float* char_emb = (const float*)d_in[6];
    const float* kb_emb   = (const float*)d_in[7];
    const float* dense_W  = (const float*)d_in[8];
    const float* dense_b  = (const float*)d_in[9];
    const float* crf_T    = (const float*)d_in[10];

    const float* f_Wcx = (const float*)d_in[11];
    const float* f_Wch = (const float*)d_in[12];
    const float* f_bc  = (const float*)d_in[13];
    const float* f_Wwx = (const float*)d_in[14];
    const float* f_Wwh = (const float*)d_in[15];
    const float* f_bw  = (const float*)d_in[16];
    const float* f_Wlx = (const float*)d_in[17];
    const float* f_Wlc = (const float*)d_in[18];
    const float* f_bl  = (const float*)d_in[19];

    const float* r_Wcx = (const float*)d_in[20];
    const float* r_Wch = (const float*)d_in[21];
    const float* r_bc  = (const float*)d_in[22];
    const float* r_Wwx = (const float*)d_in[23];
    const float* r_Wwh = (const float*)d_in[24];
    const float* r_bw  = (const float*)d_in[25];
    const float* r_Wlx = (const float*)d_in[26];
    const float* r_Wlc = (const float*)d_in[27];
    const float* r_bl  = (const float*)d_in[28];

    prep_pack_kernel<<<dim3(192, 4), 256>>>(f_Wwh, r_Wwh, f_Wlc, r_Wlc);

    char_gather_kernel<<<dim3(Bb, Ss / 8), 256>>>(char_emb, char_ids,
        f_Wcx, r_Wcx, f_Wlx, r_Wlx, f_bc, r_bc, f_bl, r_bl);
    kb_gather_kernel<<<dim3(Bb, Nn / 8), 256>>>(kb_emb, kb_ids,
        f_Wwx, r_Wwx, f_bw, r_bw);

    cudaFuncSetAttribute(lattice_kernel, cudaFuncAttributeMaxDynamicSharedMemorySize, SMEM_LAT);
    lattice_kernel<<<2 * Bb, NTHR, SMEM_LAT>>>(f_Wch, r_Wch, wbeg, wlen, slen);

    dense_kernel<<<(Bb * Ss) / 8, 256>>>(dense_W, dense_b);
    crf_kernel<<<Bb, 32>>>(label, slen, crf_T);
    finalize_kernel<<<1, 1>>>((float*)d_out);
}

// round 7
// speedup vs baseline: 2.3139x; 1.6197x over previous
#include <cuda_runtime.h>
#include <cuda_fp16.h>
#include <math.h>

#define Bb 16
#define Ss 128
#define Nn 64
#define Ee 128
#define Hh 128
#define Ll 32

// ---------------------------------------------------------------------------
// Device-global scratch
// ---------------------------------------------------------------------------
__device__ float g_Xg[(size_t)2 * Bb * Ss * 4 * Hh];   // (dir,b,t,512)
__device__ float g_Xl[(size_t)2 * Bb * Ss * Hh];       // (dir,b,t,128)
__device__ float g_Wg[(size_t)2 * Bb * Nn * 3 * Hh];   // (dir,b,n,384)
__device__ __half g_Wwh16[(size_t)2 * 128 * 384];      // (dir, (j8*384+k)*8+i), j=8*j8+i
__device__ __half g_Wlc16[(size_t)2 * 128 * 128];      // (dir, (j8*128+k)*8+i)
__device__ float g_feats[(size_t)Bb * Ss * 2 * Hh];
__device__ float g_logits[(size_t)Bb * Ss * Ll];
__device__ float g_pb[Bb];

// fast transcendentals (~2 ulp; tolerance is 1e-3)
__device__ __forceinline__ float sigf(float x) {
    return __fdividef(1.f, 1.f + __expf(-x));
}
__device__ __forceinline__ float tanhfast(float x) {
    return 1.f - 2.f * __fdividef(1.f, __expf(2.f * x) + 1.f);
}

// --- f32x2 packed helpers (sm_103a) ---------------------------------------
__device__ __forceinline__ unsigned long long packf2(float lo, float hi) {
    unsigned long long r;
    asm("mov.b64 %0, {%1, %2};" : "=l"(r) : "f"(lo), "f"(hi));
    return r;
}
__device__ __forceinline__ void unpackf2(unsigned long long v, float& lo, float& hi) {
    asm("mov.b64 {%0, %1}, %2;" : "=f"(lo), "=f"(hi) : "l"(v));
}
__device__ __forceinline__ void ffma2(unsigned long long& acc,
                                      unsigned long long a, unsigned long long b) {
    asm("fma.rn.f32x2 %0, %1, %2, %0;" : "+l"(acc) : "l"(a), "l"(b));
}

// accumulate 8 fp16 weights (one 16B quad = rows 8j..8j+7) against 8 fp32 h
__device__ __forceinline__ void dot8acc(float& acc, float4 hA, float4 hB, uint4 w) {
    float2 f0 = __half22float2(*reinterpret_cast<const __half2*>(&w.x));
    float2 f1 = __half22float2(*reinterpret_cast<const __half2*>(&w.y));
    float2 f2 = __half22float2(*reinterpret_cast<const __half2*>(&w.z));
    float2 f3 = __half22float2(*reinterpret_cast<const __half2*>(&w.w));
    acc = fmaf(hA.x, f0.x, acc); acc = fmaf(hA.y, f0.y, acc);
    acc = fmaf(hA.z, f1.x, acc); acc = fmaf(hA.w, f1.y, acc);
    acc = fmaf(hB.x, f2.x, acc); acc = fmaf(hB.y, f2.y, acc);
    acc = fmaf(hB.z, f3.x, acc); acc = fmaf(hB.w, f3.y, acc);
}

// ---------------------------------------------------------------------------
// Prep: pack Wwh/Wlc into fp16 8-row-quad layouts
// ---------------------------------------------------------------------------
__global__ void prep_pack_kernel(const float* __restrict__ fWwh,
                                 const float* __restrict__ rWwh,
                                 const float* __restrict__ fWlc,
                                 const float* __restrict__ rWlc)
{
    int which = blockIdx.y;
    int idx = blockIdx.x * 256 + threadIdx.x;
    if (which < 2) {
        const float* in = which ? rWwh : fWwh;
        __half* out = g_Wwh16 + (size_t)which * 128 * 384;
        if (idx < 128 * 384) {
            int j = idx / 384, k = idx - j * 384;
            out[((size_t)(j >> 3) * 384 + k) * 8 + (j & 7)] = __float2half(in[idx]);
        }
    } else {
        const float* in = (which == 3) ? rWlc : fWlc;
        __half* out = g_Wlc16 + (size_t)(which - 2) * 128 * 128;
        if (idx < 128 * 128) {
            int j = idx >> 7, k = idx & 127;
            out[((size_t)(j >> 3) * 128 + k) * 8 + (j & 7)] = __float2half(in[idx]);
        }
    }
}

// ---------------------------------------------------------------------------
// Fused char-side gather GEMM (unchanged)
// ---------------------------------------------------------------------------
__global__ void __launch_bounds__(256) char_gather_kernel(
    const float* __restrict__ emb, const int* __restrict__ ids,
    const float* __restrict__ fWcx, const float* __restrict__ rWcx,
    const float* __restrict__ fWlx, const float* __restrict__ rWlx,
    const float* __restrict__ fbc, const float* __restrict__ rbc,
    const float* __restrict__ fbl, const float* __restrict__ rbl)
{
    __shared__ float xs[8][128];
    int b = blockIdx.x, r0 = blockIdx.y * 8, tid = threadIdx.x;

    for (int idx = tid; idx < 8 * 128; idx += 256) {
        int r = idx >> 7, e = idx & 127;
        int id = ids[b * Ss + r0 + r];
        xs[r][e] = emb[(size_t)id * 128 + e];
    }
    __syncthreads();

    const float* wp[5];
    float bias[5];
    float* op[5];
    int ostep[5];

    wp[0] = fWcx + tid;        bias[0] = fbc[tid];
    wp[1] = fWcx + tid + 256;  bias[1] = fbc[tid + 256];
    op[0] = g_Xg + ((size_t)b * Ss + r0) * 512 + tid;
    op[1] = op[0] + 256;
    ostep[0] = ostep[1] = 512;
    wp[2] = rWcx + tid;        bias[2] = rbc[tid];
    wp[3] = rWcx + tid + 256;  bias[3] = rbc[tid + 256];
    op[2] = g_Xg + ((size_t)(Bb + b) * Ss + (Ss - 1 - r0)) * 512 + tid;
    op[3] = op[2] + 256;
    ostep[2] = ostep[3] = -512;
    if (tid < 128) {
        wp[4] = fWlx + tid; bias[4] = fbl[tid];
        op[4] = g_Xl + ((size_t)b * Ss + r0) * 128 + tid;
        ostep[4] = 128;
    } else {
        int c = tid - 128;
        wp[4] = rWlx + c; bias[4] = rbl[c];
        op[4] = g_Xl + ((size_t)(Bb + b) * Ss + (Ss - 1 - r0)) * 128 + c;
        ostep[4] = -128;
    }

    float acc[8][5];
#pragma unroll
    for (int r = 0; r < 8; r++)
#pragma unroll
        for (int s = 0; s < 5; s++) acc[r][s] = 0.f;

    for (int e = 0; e < 128; e++) {
        float w0 = wp[0][(size_t)e * 512];
        float w1 = wp[1][(size_t)e * 512];
        float w2 = wp[2][(size_t)e * 512];
        float w3 = wp[3][(size_t)e * 512];
        float w4 = wp[4][(size_t)e * 128];
#pragma unroll
        for (int r = 0; r < 8; r++) {
            float x = xs[r][e];
            acc[r][0] = fmaf(x, w0, acc[r][0]);
            acc[r][1] = fmaf(x, w1, acc[r][1]);
            acc[r][2] = fmaf(x, w2, acc[r][2]);
            acc[r][3] = fmaf(x, w3, acc[r][3]);
            acc[r][4] = fmaf(x, w4, acc[r][4]);
        }
    }

#pragma unroll
    for (int r = 0; r < 8; r++)
#pragma unroll
        for (int s = 0; s < 5; s++)
            op[s][(long)r * ostep[s]] = acc[r][s] + bias[s];
}

// ---------------------------------------------------------------------------
// Fused kb-side gather GEMM (unchanged)
// ---------------------------------------------------------------------------
__global__ void __launch_bounds__(256) kb_gather_kernel(
    const float* __restrict__ emb, const int* __restrict__ ids,
    const float* __restrict__ fW, const float* __restrict__ rW,
    const float* __restrict__ fb, const float* __restrict__ rb)
{
    __shared__ float xs[8][128];
    int b = blockIdx.x, r0 = blockIdx.y * 8, tid = threadIdx.x;

    for (int idx = tid; idx < 8 * 128; idx += 256) {
        int r = idx >> 7, e = idx & 127;
        int id = ids[b * Nn + r0 + r];
        xs[r][e] = emb[(size_t)id * 128 + e];
    }
    __syncthreads();

    const float* wp[3];
    float bias[3];
    float* op[3];
#pragma unroll
    for (int s = 0; s < 3; s++) {
        int c = tid + 256 * s;
        if (c < 384) {
            wp[s] = fW + c; bias[s] = fb[c];
            op[s] = g_Wg + ((size_t)b * Nn + r0) * 384 + c;
        } else {
            int c2 = c - 384;
            wp[s] = rW + c2; bias[s] = rb[c2];
            op[s] = g_Wg + ((size_t)(Bb + b) * Nn + r0) * 384 + c2;
        }
    }

    float acc[8][3];
#pragma unroll
    for (int r = 0; r < 8; r++)
#pragma unroll
        for (int s = 0; s < 3; s++) acc[r][s] = 0.f;

    for (int e = 0; e < 128; e++) {
        float w0 = wp[0][(size_t)e * 384];
        float w1 = wp[1][(size_t)e * 384];
        float w2 = wp[2][(size_t)e * 384];
#pragma unroll
        for (int r = 0; r < 8; r++) {
            float x = xs[r][e];
            acc[r][0] = fmaf(x, w0, acc[r][0]);
            acc[r][1] = fmaf(x, w1, acc[r][1]);
            acc[r][2] = fmaf(x, w2, acc[r][2]);
        }
    }

#pragma unroll
    for (int r = 0; r < 8; r++)
#pragma unroll
        for (int s = 0; s < 3; s++)
            op[s][(size_t)r * 384] = acc[r][s] + bias[s];
}

// ---------------------------------------------------------------------------
// Lattice LSTM: 640 threads/CTA, producer/consumer named barriers.
//   threads 0-511  : char matvec (64 fp32 reg rows + 64 fp16 smem rows)
//   threads 512-639: word path (all weights fp16 in smem) + cell update
// ---------------------------------------------------------------------------
#define NTHR 640

// smem BYTE offsets
#define OFF_WCH   0                    // 64*512 fp16 = 65536
#define OFF_WWH   65536                // 384*128 fp16 = 98304
#define OFF_WLC   163840               // 128*128 fp16 = 32768
#define OFF_H     196608               // 8*128 f32 = 4096
#define OFF_C     200704               // 4096
#define OFF_G     204800               // 512 f32 = 2048
#define OFF_CW    206848               // 512
#define OFF_SE    207360               // 512
#define OFF_SC    207872               // 512
#define OFF_INT   208384               // 449 ints = 1796
#define SMEM_LAT  210192

#define BAR_SYNC2()   asm volatile("bar.sync 2, 640;" ::: "memory")
#define BAR_ARRIVE2() asm volatile("bar.arrive 2, 640;" ::: "memory")
#define BAR_SYNC3()   asm volatile("bar.sync 3, 640;" ::: "memory")
#define BAR_ARRIVE3() asm volatile("bar.arrive 3, 640;" ::: "memory")

__global__ void __launch_bounds__(NTHR, 1) lattice_kernel(
    const float* __restrict__ Wch_f, const float* __restrict__ Wch_r,
    const int* __restrict__ word_begin, const int* __restrict__ word_len,
    const int* __restrict__ seqlen)
{
    extern __shared__ char smraw[];
    __half* wch_h   = (__half*)(smraw + OFF_WCH);
    __half* wwh_h   = (__half*)(smraw + OFF_WWH);
    __half* wlc_h   = (__half*)(smraw + OFF_WLC);
    float* h_ring   = (float*)(smraw + OFF_H);
    float* c_ring   = (float*)(smraw + OFF_C);
    float* gates    = (float*)(smraw + OFF_G);
    float* cw       = (float*)(smraw + OFF_CW);
    float* sum_ew   = (float*)(smraw + OFF_SE);
    float* sum_ewcw = (float*)(smraw + OFF_SC);
    int* ip        = (int*)(smraw + OFF_INT);
    int* w_beg     = ip;
    int* w_end     = ip + 64;
    int* wl_start  = ip + 128;
    int* wl_idx    = ip + 257;
    int* cur       = ip + 321;

    int dirb = blockIdx.x;
    int dir  = dirb / Bb;
    int b    = dirb - dir * Bb;
    int tid  = threadIdx.x;
    int sl   = seqlen[b];

    const float* Wch  = dir ? Wch_r : Wch_f;
    const float* Xg_b = g_Xg + (size_t)dirb * Ss * 512;
    const float* Xl_b = g_Xl + (size_t)dirb * Ss * 128;
    const float* Wg_b = g_Wg + (size_t)dirb * Nn * 384;

    // Wch rows 64..127 -> fp16 smem, 8-row quads per column
    for (int i = tid; i < 64 * 512; i += NTHR) {
        int r = i >> 9, c = i & 511;
        wch_h[(((r >> 3) * 512 + c) << 3) + (r & 7)] =
            __float2half(Wch[(size_t)(64 + r) * 512 + c]);
    }
    // copy prepacked Wwh/Wlc fp16 into smem
    {
        const uint4* src = (const uint4*)(g_Wwh16 + (size_t)dir * 128 * 384);
        uint4* dst = (uint4*)wwh_h;
        for (int i = tid; i < 128 * 384 / 8; i += NTHR) dst[i] = src[i];
        const uint4* src2 = (const uint4*)(g_Wlc16 + (size_t)dir * 128 * 128);
        uint4* dst2 = (uint4*)wlc_h;
        for (int i = tid; i < 128 * 128 / 8; i += NTHR) dst2[i] = src2[i];
    }

    // Wch rows 0..63 fp32 in registers (char threads)
    unsigned long long wregp[32];
    if (tid < 512) {
#pragma unroll
        for (int r = 0; r < 32; r++)
            wregp[r] = packf2(Wch[(size_t)(2 * r) * 512 + tid],
                              Wch[(size_t)(2 * r + 1) * 512 + tid]);
    }

    int t0 = dir ? (Ss - sl) : 0;
    int t1 = dir ? Ss : sl;

    if (tid >= 512) {
        int k = tid - 512;
        h_ring[(t0 & 7) * Hh + k] = 0.f;
        c_ring[(t0 & 7) * Hh + k] = 0.f;
    }

    // zero masked feats rows
    for (int i = tid; i < (Ss - sl) * Hh; i += NTHR) {
        int row = sl + (i >> 7), col = i & 127;
        g_feats[((size_t)b * Ss + row) * (2 * Hh) + dir * Hh + col] = 0.f;
    }

    if (tid < Nn) {
        int bg = word_begin[b * Nn + tid];
        int ln = word_len[b * Nn + tid];
        int ef = min(bg + ln, Ss - 1);
        bool valid = ef < sl;
        if (dir == 0) {
            w_beg[tid] = bg;
            w_end[tid] = valid ? ef : -1;
        } else {
            w_beg[tid] = Ss - 1 - ef;
            w_end[tid] = valid ? (Ss - 1 - bg) : -1;
        }
    }
    __syncthreads();

    if (tid == 0) {
        for (int t = 0; t < Ss; t++) cur[t] = 0;
        for (int n = 0; n < Nn; n++) { int e = w_end[n]; if (e >= 0) cur[e]++; }
        wl_start[0] = 0;
        for (int t = 0; t < Ss; t++) wl_start[t + 1] = wl_start[t] + cur[t];
        for (int t = 0; t < Ss; t++) cur[t] = wl_start[t];
        for (int n = 0; n < Nn; n++) { int e = w_end[n]; if (e >= 0) wl_idx[cur[e]++] = n; }
    }
    __syncthreads();

    // prime the state-ready barrier so char's first BAR_SYNC2 passes
    if (tid >= 512) BAR_ARRIVE2();

    const ulonglong2* wq16 = nullptr;
    const uint4* w8 = (const uint4*)wch_h;
    const uint4* ww = (const uint4*)wwh_h;
    const uint4* wl = (const uint4*)wlc_h;
    (void)wq16;

    float xg = (tid < 512) ? Xg_b[(size_t)t0 * 512 + tid] : 0.f;

    for (int t = t0; t < t1; t++) {
        int curS = (t & 7) * Hh;
        int nxtS = ((t + 1) & 7) * Hh;
        int wls = wl_start[t];
        int m = wl_start[t + 1] - wls;

        if (tid < 512) {
            BAR_SYNC2();                 // wait: state for step t ready
            float xg_cur = xg;
            if (t + 1 < t1) xg = Xg_b[(size_t)(t + 1) * 512 + tid];

            // rows 0..63 from registers (f32x2)
            const ulonglong2* hh = (const ulonglong2*)(h_ring + curS);
            unsigned long long accA = packf2(xg_cur, 0.f);
            unsigned long long accB = packf2(0.f, 0.f);
#pragma unroll
            for (int k = 0; k < 16; k++) {
                ulonglong2 hq = hh[k];
                ffma2(accA, hq.x, wregp[2 * k]);
                ffma2(accB, hq.y, wregp[2 * k + 1]);
            }
            // rows 64..127 from fp16 smem
            const float4* h4f = (const float4*)(h_ring + curS);
            float s0 = 0.f, s1 = 0.f;
#pragma unroll
            for (int q = 0; q < 8; q += 2) {
                dot8acc(s0, h4f[16 + 2 * q],     h4f[17 + 2 * q],     w8[q * 512 + tid]);
                dot8acc(s1, h4f[18 + 2 * q],     h4f[19 + 2 * q],     w8[(q + 1) * 512 + tid]);
            }
            float a0, a1, b0, b1;
            unpackf2(accA, a0, a1);
            unpackf2(accB, b0, b1);
            gates[tid] = (a0 + a1) + (b0 + b1) + (s0 + s1);
            BAR_ARRIVE3();               // gates ready
        } else {
            int wt = tid - 512;
            if (m > 0) {
                float sew = 0.f, sewc = 0.f;
                for (int wv = 0; wv < m; wv++) {
                    int n   = wl_idx[wls + wv];
                    int bgS = (w_beg[n] & 7) * Hh;
                    float xl = __ldg(Xl_b + (size_t)t * 128 + wt);
                    const float4* hb4 = (const float4*)(h_ring + bgS);
                    float acc0 = __ldg(Wg_b + (size_t)n * 384 + wt);
                    float acc1 = __ldg(Wg_b + (size_t)n * 384 + wt + 128);
                    float acc2 = __ldg(Wg_b + (size_t)n * 384 + wt + 256);
#pragma unroll 4
                    for (int j8 = 0; j8 < 16; j8++) {
                        float4 hA = hb4[2 * j8], hB = hb4[2 * j8 + 1];
                        dot8acc(acc0, hA, hB, ww[j8 * 384 + wt]);
                        dot8acc(acc1, hA, hB, ww[j8 * 384 + wt + 128]);
                        dot8acc(acc2, hA, hB, ww[j8 * 384 + wt + 256]);
                    }
                    float cwv = sigf(acc1) * c_ring[bgS + wt] + sigf(acc0) * tanhfast(acc2);
                    cw[wt] = cwv;
                    asm volatile("bar.sync 1, 128;" ::: "memory");
                    const float4* c4 = (const float4*)cw;
                    float q0 = 0.f, q1 = 0.f;
#pragma unroll 4
                    for (int j8 = 0; j8 < 16; j8 += 2) {
                        dot8acc(q0, c4[2 * j8],     c4[2 * j8 + 1], wl[j8 * 128 + wt]);
                        dot8acc(q1, c4[2 * j8 + 2], c4[2 * j8 + 3], wl[(j8 + 1) * 128 + wt]);
                    }
                    float ew = __expf(sigf(xl + q0 + q1));
                    sew  += ew;
                    sewc += ew * cwv;
                    asm volatile("bar.sync 1, 128;" ::: "memory");
                }
                sum_ew[wt] = sew;
                sum_ewcw[wt] = sewc;
            }
            BAR_SYNC3();                 // wait: gates ready
            // cell/state update
            int k = wt;
            float ig = sigf(gates[k]);
            float fg = sigf(gates[Hh + k]);
            float og = sigf(gates[2 * Hh + k]);
            float gg = tanhfast(gates[3 * Hh + k]);
            float cp = c_ring[curS + k];
            float ct;
            if (m > 0) {
                float ec = __expf(ig);
                ct = __fdividef(ec * gg + sum_ewcw[k], ec + sum_ew[k]);
            } else {
                ct = fg * cp + ig * gg;
            }
            float ht = og * tanhfast(ct);
            h_ring[nxtS + k] = ht;
            c_ring[nxtS + k] = ct;
            int tt = (dir == 0) ? t : (Ss - 1 - t);
            g_feats[((size_t)b * Ss + tt) * (2 * Hh) + dir * Hh + k] = ht;
            BAR_ARRIVE2();               // state for step t+1 ready
        }
    }
}

// ---------------------------------------------------------------------------
// Dense projection
// ---------------------------------------------------------------------------
__global__ void dense_kernel(const float* __restrict__ W, const float* __restrict__ bias)
{
    __shared__ float fs[8][2 * Hh];
    int row0 = blockIdx.x * 8;
    int tid = threadIdx.x;
    for (int idx = tid; idx < 8 * 2 * Hh; idx += 256) {
        int r = idx >> 8;
        int e = idx & 255;
        fs[r][e] = g_feats[(size_t)(row0 + r) * (2 * Hh) + e];
    }
    __syncthreads();
    int r = tid >> 5;
    int col = tid & 31;
    float acc = bias[col];
#pragma unroll 8
    for (int e = 0; e < 2 * Hh; e++) acc = fmaf(fs[r][e], W[e * Ll + col], acc);
    g_logits[(size_t)(row0 + r) * Ll + col] = acc;
}

// ---------------------------------------------------------------------------
// CRF
// ---------------------------------------------------------------------------
__global__ void crf_kernel(const int* __restrict__ label,
                           const int* __restrict__ seqlen,
                           const float* __restrict__ T)
{
    int b = blockIdx.x;
    int j = threadIdx.x;
    int sl = seqlen[b];
    const float* lg = g_logits + (size_t)b * Ss * Ll;
    const int*   lab = label + b * Ss;

    float Tc[32];
#pragma unroll
    for (int i = 0; i < 32; i++) Tc[i] = T[i * Ll + j];

    float gold = 0.f;
    for (int t = j; t < Ss; t += 32)
        if (t < sl) gold += lg[t * Ll + lab[t]];
    for (int t = j + 1; t < Ss; t += 32)
        if (t < sl) gold += T[lab[t - 1] * Ll + lab[t]];
#pragma unroll
    for (int o = 16; o; o >>= 1) gold += __shfl_xor_sync(0xffffffffu, gold, o);

    float alpha = lg[j];
    for (int t = 1; t < Ss; t++) {
        float vmax = -1e30f;
#pragma unroll
        for (int i = 0; i < 32; i++) {
            float ai = __shfl_sync(0xffffffffu, alpha, i);
            vmax = fmaxf(vmax, ai + Tc[i]);
        }
        float s = 0.f;
#pragma unroll
        for (int i = 0; i < 32; i++) {
            float ai = __shfl_sync(0xffffffffu, alpha, i);
            s += expf(ai + Tc[i] - vmax);
        }
        float na = vmax + logf(s) + lg[(size_t)t * Ll + j];
        if (t < sl) alpha = na;
    }
    float m2 = alpha;
#pragma unroll
    for (int o = 16; o; o >>= 1) m2 = fmaxf(m2, __shfl_xor_sync(0xffffffffu, m2, o));
    float s2 = expf(alpha - m2);
#pragma unroll
    for (int o = 16; o; o >>= 1) s2 += __shfl_xor_sync(0xffffffffu, s2, o);
    if (j == 0) g_pb[b] = (m2 + logf(s2)) - gold;
}

__global__ void finalize_kernel(float* __restrict__ out)
{
    float s = 0.f;
#pragma unroll
    for (int i = 0; i < Bb; i++) s += g_pb[i];
    out[0] = s / (float)Bb;
}

// ---------------------------------------------------------------------------
// Launch
// ---------------------------------------------------------------------------
extern "C" void kernel_launch(void* const* d_in, const int* in_sizes, int n_in,
                              void* d_out, int out_size)
{
    const int* char_ids = (const int*)d_in[0];
    const int* kb_ids   = (const int*)d_in[1];
    const int* wbeg     = (const int*)d_in[2];
    const int* wlen     = (const int*)d_in[3];
    const int* label    = (const int*)d_in[4];
    const int* slen     = (const int*)d_in[5];
    const float* char_emb = (const float*)d_in[6];
    const float* kb_emb   = (const float*)d_in[7];
    const float* dense_W  = (const float*)d_in[8];
    const float* dense_b  = (const float*)d_in[9];
    const float* crf_T    = (const float*)d_in[10];

    const float* f_Wcx = (const float*)d_in[11];
    const float* f_Wch = (const float*)d_in[12];
    const float* f_bc  = (const float*)d_in[13];
    const float* f_Wwx = (const float*)d_in[14];
    const float* f_Wwh = (const float*)d_in[15];
    const float* f_bw  = (const float*)d_in[16];
    const float* f_Wlx = (const float*)d_in[17];
    const float* f_Wlc = (const float*)d_in[18];
    const float* f_bl  = (const float*)d_in[19];

    const float* r_Wcx = (const float*)d_in[20];
    const float* r_Wch = (const float*)d_in[21];
    const float* r_bc  = (const float*)d_in[22];
    const float* r_Wwx = (const float*)d_in[23];
    const float* r_Wwh = (const float*)d_in[24];
    const float* r_bw  = (const float*)d_in[25];
    const float* r_Wlx = (const float*)d_in[26];
    const float* r_Wlc = (const float*)d_in[27];
    const float* r_bl  = (const float*)d_in[28];

    prep_pack_kernel<<<dim3(192, 4), 256>>>(f_Wwh, r_Wwh, f_Wlc, r_Wlc);

    char_gather_kernel<<<dim3(Bb, Ss / 8), 256>>>(char_emb, char_ids,
        f_Wcx, r_Wcx, f_Wlx, r_Wlx, f_bc, r_bc, f_bl, r_bl);
    kb_gather_kernel<<<dim3(Bb, Nn / 8), 256>>>(kb_emb, kb_ids,
        f_Wwx, r_Wwx, f_bw, r_bw);

    cudaFuncSetAttribute(lattice_kernel, cudaFuncAttributeMaxDynamicSharedMemorySize, SMEM_LAT);
    lattice_kernel<<<2 * Bb, NTHR, SMEM_LAT>>>(f_Wch, r_Wch, wbeg, wlen, slen);

    dense_kernel<<<(Bb * Ss) / 8, 256>>>(dense_W, dense_b);
    crf_kernel<<<Bb, 32>>>(label, slen, crf_T);
    finalize_kernel<<<1, 1>>>((float*)d_out);
}

// round 8
// speedup vs baseline: 2.3613x; 1.0205x over previous
#include <cuda_runtime.h>
#include <cuda_fp16.h>
#include <math.h>

#define Bb 16
#define Ss 128
#define Nn 64
#define Ee 128
#define Hh 128
#define Ll 32

// ---------------------------------------------------------------------------
// Device-global scratch
// ---------------------------------------------------------------------------
__device__ float g_Xg[(size_t)2 * Bb * Ss * 4 * Hh];   // (dir,b,t,512)
__device__ float g_Xl[(size_t)2 * Bb * Ss * Hh];       // (dir,b,t,128)
__device__ float g_Wg[(size_t)2 * Bb * Nn * 3 * Hh];   // (dir,b,n,384)
__device__ __half g_Wwh16[(size_t)2 * 128 * 384];      // (dir, (j8*384+k)*8+i)
__device__ __half g_Wlc16[(size_t)2 * 128 * 128];      // (dir, (j8*128+k)*8+i)
__device__ float g_feats[(size_t)Bb * Ss * 2 * Hh];
__device__ float g_logits[(size_t)Bb * Ss * Ll];
__device__ float g_pb[Bb];

// fast transcendentals (~2 ulp; tolerance is 1e-3)
__device__ __forceinline__ float sigf(float x) {
    return __fdividef(1.f, 1.f + __expf(-x));
}
__device__ __forceinline__ float tanhfast(float x) {
    return 1.f - 2.f * __fdividef(1.f, __expf(2.f * x) + 1.f);
}

// accumulate 8 fp16 weights (one 16B quad = rows 8j..8j+7) against 8 fp32 h
__device__ __forceinline__ void dot8acc(float& acc, float4 hA, float4 hB, uint4 w) {
    float2 f0 = __half22float2(*reinterpret_cast<const __half2*>(&w.x));
    float2 f1 = __half22float2(*reinterpret_cast<const __half2*>(&w.y));
    float2 f2 = __half22float2(*reinterpret_cast<const __half2*>(&w.z));
    float2 f3 = __half22float2(*reinterpret_cast<const __half2*>(&w.w));
    acc = fmaf(hA.x, f0.x, acc); acc = fmaf(hA.y, f0.y, acc);
    acc = fmaf(hA.z, f1.x, acc); acc = fmaf(hA.w, f1.y, acc);
    acc = fmaf(hB.x, f2.x, acc); acc = fmaf(hB.y, f2.y, acc);
    acc = fmaf(hB.z, f3.x, acc); acc = fmaf(hB.w, f3.y, acc);
}

// ---------------------------------------------------------------------------
// Prep: pack Wwh/Wlc into fp16 8-row-quad layouts
// ---------------------------------------------------------------------------
__global__ void prep_pack_kernel(const float* __restrict__ fWwh,
                                 const float* __restrict__ rWwh,
                                 const float* __restrict__ fWlc,
                                 const float* __restrict__ rWlc)
{
    int which = blockIdx.y;
    int idx = blockIdx.x * 256 + threadIdx.x;
    if (which < 2) {
        const float* in = which ? rWwh : fWwh;
        __half* out = g_Wwh16 + (size_t)which * 128 * 384;
        if (idx < 128 * 384) {
            int j = idx / 384, k = idx - j * 384;
            out[((size_t)(j >> 3) * 384 + k) * 8 + (j & 7)] = __float2half(in[idx]);
        }
    } else {
        const float* in = (which == 3) ? rWlc : fWlc;
        __half* out = g_Wlc16 + (size_t)(which - 2) * 128 * 128;
        if (idx < 128 * 128) {
            int j = idx >> 7, k = idx & 127;
            out[((size_t)(j >> 3) * 128 + k) * 8 + (j & 7)] = __float2half(in[idx]);
        }
    }
}

// ---------------------------------------------------------------------------
// Fused char-side gather GEMM (unchanged)
// ---------------------------------------------------------------------------
__global__ void __launch_bounds__(256) char_gather_kernel(
    const float* __restrict__ emb, const int* __restrict__ ids,
    const float* __restrict__ fWcx, const float* __restrict__ rWcx,
    const float* __restrict__ fWlx, const float* __restrict__ rWlx,
    const float* __restrict__ fbc, const float* __restrict__ rbc,
    const float* __restrict__ fbl, const float* __restrict__ rbl)
{
    __shared__ float xs[8][128];
    int b = blockIdx.x, r0 = blockIdx.y * 8, tid = threadIdx.x;

    for (int idx = tid; idx < 8 * 128; idx += 256) {
        int r = idx >> 7, e = idx & 127;
        int id = ids[b * Ss + r0 + r];
        xs[r][e] = emb[(size_t)id * 128 + e];
    }
    __syncthreads();

    const float* wp[5];
    float bias[5];
    float* op[5];
    int ostep[5];

    wp[0] = fWcx + tid;        bias[0] = fbc[tid];
    wp[1] = fWcx + tid + 256;  bias[1] = fbc[tid + 256];
    op[0] = g_Xg + ((size_t)b * Ss + r0) * 512 + tid;
    op[1] = op[0] + 256;
    ostep[0] = ostep[1] = 512;
    wp[2] = rWcx + tid;        bias[2] = rbc[tid];
    wp[3] = rWcx + tid + 256;  bias[3] = rbc[tid + 256];
    op[2] = g_Xg + ((size_t)(Bb + b) * Ss + (Ss - 1 - r0)) * 512 + tid;
    op[3] = op[2] + 256;
    ostep[2] = ostep[3] = -512;
    if (tid < 128) {
        wp[4] = fWlx + tid; bias[4] = fbl[tid];
        op[4] = g_Xl + ((size_t)b * Ss + r0) * 128 + tid;
        ostep[4] = 128;
    } else {
        int c = tid - 128;
        wp[4] = rWlx + c; bias[4] = rbl[c];
        op[4] = g_Xl + ((size_t)(Bb + b) * Ss + (Ss - 1 - r0)) * 128 + c;
        ostep[4] = -128;
    }

    float acc[8][5];
#pragma unroll
    for (int r = 0; r < 8; r++)
#pragma unroll
        for (int s = 0; s < 5; s++) acc[r][s] = 0.f;

    for (int e = 0; e < 128; e++) {
        float w0 = wp[0][(size_t)e * 512];
        float w1 = wp[1][(size_t)e * 512];
        float w2 = wp[2][(size_t)e * 512];
        float w3 = wp[3][(size_t)e * 512];
        float w4 = wp[4][(size_t)e * 128];
#pragma unroll
        for (int r = 0; r < 8; r++) {
            float x = xs[r][e];
            acc[r][0] = fmaf(x, w0, acc[r][0]);
            acc[r][1] = fmaf(x, w1, acc[r][1]);
            acc[r][2] = fmaf(x, w2, acc[r][2]);
            acc[r][3] = fmaf(x, w3, acc[r][3]);
            acc[r][4] = fmaf(x, w4, acc[r][4]);
        }
    }

#pragma unroll
    for (int r = 0; r < 8; r++)
#pragma unroll
        for (int s = 0; s < 5; s++)
            op[s][(long)r * ostep[s]] = acc[r][s] + bias[s];
}

// ---------------------------------------------------------------------------
// Fused kb-side gather GEMM (unchanged)
// ---------------------------------------------------------------------------
__global__ void __launch_bounds__(256) kb_gather_kernel(
    const float* __restrict__ emb, const int* __restrict__ ids,
    const float* __restrict__ fW, const float* __restrict__ rW,
    const float* __restrict__ fb, const float* __restrict__ rb)
{
    __shared__ float xs[8][128];
    int b = blockIdx.x, r0 = blockIdx.y * 8, tid = threadIdx.x;

    for (int idx = tid; idx < 8 * 128; idx += 256) {
        int r = idx >> 7, e = idx & 127;
        int id = ids[b * Nn + r0 + r];
        xs[r][e] = emb[(size_t)id * 128 + e];
    }
    __syncthreads();

    const float* wp[3];
    float bias[3];
    float* op[3];
#pragma unroll
    for (int s = 0; s < 3; s++) {
        int c = tid + 256 * s;
        if (c < 384) {
            wp[s] = fW + c; bias[s] = fb[c];
            op[s] = g_Wg + ((size_t)b * Nn + r0) * 384 + c;
        } else {
            int c2 = c - 384;
            wp[s] = rW + c2; bias[s] = rb[c2];
            op[s] = g_Wg + ((size_t)(Bb + b) * Nn + r0) * 384 + c2;
        }
    }

    float acc[8][3];
#pragma unroll
    for (int r = 0; r < 8; r++)
#pragma unroll
        for (int s = 0; s < 3; s++) acc[r][s] = 0.f;

    for (int e = 0; e < 128; e++) {
        float w0 = wp[0][(size_t)e * 384];
        float w1 = wp[1][(size_t)e * 384];
        float w2 = wp[2][(size_t)e * 384];
#pragma unroll
        for (int r = 0; r < 8; r++) {
            float x = xs[r][e];
            acc[r][0] = fmaf(x, w0, acc[r][0]);
            acc[r][1] = fmaf(x, w1, acc[r][1]);
            acc[r][2] = fmaf(x, w2, acc[r][2]);
        }
    }

#pragma unroll
    for (int r = 0; r < 8; r++)
#pragma unroll
        for (int s = 0; s < 3; s++)
            op[s][(size_t)r * 384] = acc[r][s] + bias[s];
}

// ---------------------------------------------------------------------------
// Lattice LSTM: 640 threads/CTA, producer/consumer named barriers.
//   threads 0-511  : char matvec — ALL 128 Wch rows fp16 in registers
//                    (64 half2 = 64 regs), h via 32 broadcast LDS.128.
//                    Gate nonlinearities applied here (warp-uniform).
//   threads 512-639: word path (fp16 smem weights) + cell update
// ---------------------------------------------------------------------------
#define NTHR 640

// smem BYTE offsets
#define OFF_WWH   0                    // 384*128 fp16 = 98304
#define OFF_WLC   98304                // 128*128 fp16 = 32768
#define OFF_H     131072               // 8*128 f32 = 4096
#define OFF_C     135168               // 4096
#define OFF_G     139264               // 512 f32 = 2048
#define OFF_CW    141312               // 512
#define OFF_SE    141824               // 512
#define OFF_SC    142336               // 512
#define OFF_INT   142848               // 449 ints = 1796
#define SMEM_LAT  144644

#define BAR_SYNC2()   asm volatile("bar.sync 2, 640;" ::: "memory")
#define BAR_ARRIVE2() asm volatile("bar.arrive 2, 640;" ::: "memory")
#define BAR_SYNC3()   asm volatile("bar.sync 3, 640;" ::: "memory")
#define BAR_ARRIVE3() asm volatile("bar.arrive 3, 640;" ::: "memory")

__global__ void __launch_bounds__(NTHR, 1) lattice_kernel(
    const float* __restrict__ Wch_f, const float* __restrict__ Wch_r,
    const int* __restrict__ word_begin, const int* __restrict__ word_len,
    const int* __restrict__ seqlen)
{
    extern __shared__ char smraw[];
    __half* wwh_h   = (__half*)(smraw + OFF_WWH);
    __half* wlc_h   = (__half*)(smraw + OFF_WLC);
    float* h_ring   = (float*)(smraw + OFF_H);
    float* c_ring   = (float*)(smraw + OFF_C);
    float* gates    = (float*)(smraw + OFF_G);
    float* cw       = (float*)(smraw + OFF_CW);
    float* sum_ew   = (float*)(smraw + OFF_SE);
    float* sum_ewcw = (float*)(smraw + OFF_SC);
    int* ip        = (int*)(smraw + OFF_INT);
    int* w_beg     = ip;
    int* w_end     = ip + 64;
    int* wl_start  = ip + 128;
    int* wl_idx    = ip + 257;
    int* cur       = ip + 321;

    int dirb = blockIdx.x;
    int dir  = dirb / Bb;
    int b    = dirb - dir * Bb;
    int tid  = threadIdx.x;
    int sl   = seqlen[b];

    const float* Wch  = dir ? Wch_r : Wch_f;
    const float* Xg_b = g_Xg + (size_t)dirb * Ss * 512;
    const float* Xl_b = g_Xl + (size_t)dirb * Ss * 128;
    const float* Wg_b = g_Wg + (size_t)dirb * Nn * 384;

    // copy prepacked Wwh/Wlc fp16 into smem
    {
        const uint4* src = (const uint4*)(g_Wwh16 + (size_t)dir * 128 * 384);
        uint4* dst = (uint4*)wwh_h;
        for (int i = tid; i < 128 * 384 / 8; i += NTHR) dst[i] = src[i];
        const uint4* src2 = (const uint4*)(g_Wlc16 + (size_t)dir * 128 * 128);
        uint4* dst2 = (uint4*)wlc_h;
        for (int i = tid; i < 128 * 128 / 8; i += NTHR) dst2[i] = src2[i];
    }

    // ALL 128 Wch rows for column tid -> 64 half2 registers (char threads)
    __half2 wh[64];
    if (tid < 512) {
#pragma unroll
        for (int j = 0; j < 64; j++)
            wh[j] = __floats2half2_rn(Wch[(size_t)(2 * j) * 512 + tid],
                                      Wch[(size_t)(2 * j + 1) * 512 + tid]);
    }

    int t0 = dir ? (Ss - sl) : 0;
    int t1 = dir ? Ss : sl;

    if (tid >= 512) {
        int k = tid - 512;
        h_ring[(t0 & 7) * Hh + k] = 0.f;
        c_ring[(t0 & 7) * Hh + k] = 0.f;
    }

    // zero masked feats rows
    for (int i = tid; i < (Ss - sl) * Hh; i += NTHR) {
        int row = sl + (i >> 7), col = i & 127;
        g_feats[((size_t)b * Ss + row) * (2 * Hh) + dir * Hh + col] = 0.f;
    }

    if (tid < Nn) {
        int bg = word_begin[b * Nn + tid];
        int ln = word_len[b * Nn + tid];
        int ef = min(bg + ln, Ss - 1);
        bool valid = ef < sl;
        if (dir == 0) {
            w_beg[tid] = bg;
            w_end[tid] = valid ? ef : -1;
        } else {
            w_beg[tid] = Ss - 1 - ef;
            w_end[tid] = valid ? (Ss - 1 - bg) : -1;
        }
    }
    __syncthreads();

    if (tid == 0) {
        for (int t = 0; t < Ss; t++) cur[t] = 0;
        for (int n = 0; n < Nn; n++) { int e = w_end[n]; if (e >= 0) cur[e]++; }
        wl_start[0] = 0;
        for (int t = 0; t < Ss; t++) wl_start[t + 1] = wl_start[t] + cur[t];
        for (int t = 0; t < Ss; t++) cur[t] = wl_start[t];
        for (int n = 0; n < Nn; n++) { int e = w_end[n]; if (e >= 0) wl_idx[cur[e]++] = n; }
    }
    __syncthreads();

    // prime the state-ready barrier so char's first BAR_SYNC2 passes
    if (tid >= 512) BAR_ARRIVE2();

    const uint4* ww = (const uint4*)wwh_h;
    const uint4* wl = (const uint4*)wlc_h;

    float xg = (tid < 512) ? Xg_b[(size_t)t0 * 512 + tid] : 0.f;
    int gt = tid >> 7;   // 0,1,2 = sigmoid gates; 3 = tanh gate (warp-uniform)

    for (int t = t0; t < t1; t++) {
        int curS = (t & 7) * Hh;
        int nxtS = ((t + 1) & 7) * Hh;
        int wls = wl_start[t];
        int m = wl_start[t + 1] - wls;

        if (tid < 512) {
            BAR_SYNC2();                 // wait: state for step t ready
            float xg_cur = xg;
            if (t + 1 < t1) xg = Xg_b[(size_t)(t + 1) * 512 + tid];

            const float4* h4 = (const float4*)(h_ring + curS);
            float acc0 = xg_cur, acc1 = 0.f;
#pragma unroll
            for (int q = 0; q < 32; q++) {
                float4 hv = h4[q];
                float2 w0 = __half22float2(wh[2 * q]);
                float2 w1 = __half22float2(wh[2 * q + 1]);
                acc0 = fmaf(hv.x, w0.x, acc0);
                acc0 = fmaf(hv.y, w0.y, acc0);
                acc1 = fmaf(hv.z, w1.x, acc1);
                acc1 = fmaf(hv.w, w1.y, acc1);
            }
            float gv = acc0 + acc1;
            gates[tid] = (gt == 3) ? tanhfast(gv) : sigf(gv);
            BAR_ARRIVE3();               // activated gates ready
        } else {
            int wt = tid - 512;
            if (m > 0) {
                float sew = 0.f, sewc = 0.f;
                for (int wv = 0; wv < m; wv++) {
                    int n   = wl_idx[wls + wv];
                    int bgS = (w_beg[n] & 7) * Hh;
                    float xl = __ldg(Xl_b + (size_t)t * 128 + wt);
                    const float4* hb4 = (const float4*)(h_ring + bgS);
                    float acc0 = __ldg(Wg_b + (size_t)n * 384 + wt);
                    float acc1 = __ldg(Wg_b + (size_t)n * 384 + wt + 128);
                    float acc2 = __ldg(Wg_b + (size_t)n * 384 + wt + 256);
#pragma unroll 4
                    for (int j8 = 0; j8 < 16; j8++) {
                        float4 hA = hb4[2 * j8], hB = hb4[2 * j8 + 1];
                        dot8acc(acc0, hA, hB, ww[j8 * 384 + wt]);
                        dot8acc(acc1, hA, hB, ww[j8 * 384 + wt + 128]);
                        dot8acc(acc2, hA, hB, ww[j8 * 384 + wt + 256]);
                    }
                    float cwv = sigf(acc1) * c_ring[bgS + wt] + sigf(acc0) * tanhfast(acc2);
                    cw[wt] = cwv;
                    asm volatile("bar.sync 1, 128;" ::: "memory");
                    const float4* c4 = (const float4*)cw;
                    float q0 = 0.f, q1 = 0.f;
#pragma unroll 4
                    for (int j8 = 0; j8 < 16; j8 += 2) {
                        dot8acc(q0, c4[2 * j8],     c4[2 * j8 + 1], wl[j8 * 128 + wt]);
                        dot8acc(q1, c4[2 * j8 + 2], c4[2 * j8 + 3], wl[(j8 + 1) * 128 + wt]);
                    }
                    float ew = __expf(sigf(xl + q0 + q1));
                    sew  += ew;
                    sewc += ew * cwv;
                    asm volatile("bar.sync 1, 128;" ::: "memory");
                }
                sum_ew[wt] = sew;
                sum_ewcw[wt] = sewc;
            }
            BAR_SYNC3();                 // wait: activated gates ready
            // cell/state update (gates already activated)
            int k = wt;
            float ig = gates[k];
            float fg = gates[Hh + k];
            float og = gates[2 * Hh + k];
            float gg = gates[3 * Hh + k];
            float cp = c_ring[curS + k];
            float ct;
            if (m > 0) {
                float ec = __expf(ig);
                ct = __fdividef(ec * gg + sum_ewcw[k], ec + sum_ew[k]);
            } else {
                ct = fg * cp + ig * gg;
            }
            float ht = og * tanhfast(ct);
            h_ring[nxtS + k] = ht;
            c_ring[nxtS + k] = ct;
            int tt = (dir == 0) ? t : (Ss - 1 - t);
            g_feats[((size_t)b * Ss + tt) * (2 * Hh) + dir * Hh + k] = ht;
            BAR_ARRIVE2();               // state for step t+1 ready
        }
    }
}

// ---------------------------------------------------------------------------
// Dense projection
// ---------------------------------------------------------------------------
__global__ void dense_kernel(const float* __restrict__ W, const float* __restrict__ bias)
{
    __shared__ float fs[8][2 * Hh];
    int row0 = blockIdx.x * 8;
    int tid = threadIdx.x;
    for (int idx = tid; idx < 8 * 2 * Hh; idx += 256) {
        int r = idx >> 8;
        int e = idx & 255;
        fs[r][e] = g_feats[(size_t)(row0 + r) * (2 * Hh) + e];
    }
    __syncthreads();
    int r = tid >> 5;
    int col = tid & 31;
    float acc = bias[col];
#pragma unroll 8
    for (int e = 0; e < 2 * Hh; e++) acc = fmaf(fs[r][e], W[e * Ll + col], acc);
    g_logits[(size_t)(row0 + r) * Ll + col] = acc;
}

// ---------------------------------------------------------------------------
// CRF
// ---------------------------------------------------------------------------
__global__ void crf_kernel(const int* __restrict__ label,
                           const int* __restrict__ seqlen,
                           const float* __restrict__ T)
{
    int b = blockIdx.x;
    int j = threadIdx.x;
    int sl = seqlen[b];
    const float* lg = g_logits + (size_t)b * Ss * Ll;
    const int*   lab = label + b * Ss;

    float Tc[32];
#pragma unroll
    for (int i = 0; i < 32; i++) Tc[i] = T[i * Ll + j];

    float gold = 0.f;
    for (int t = j; t < Ss; t += 32)
        if (t < sl) gold += lg[t * Ll + lab[t]];
    for (int t = j + 1; t < Ss; t += 32)
        if (t < sl) gold += T[lab[t - 1] * Ll + lab[t]];
#pragma unroll
    for (int o = 16; o; o >>= 1) gold += __shfl_xor_sync(0xffffffffu, gold, o);

    float alpha = lg[j];
    for (int t = 1; t < Ss; t++) {
        float vmax = -1e30f;
#pragma unroll
        for (int i = 0; i < 32; i++) {
            float ai = __shfl_sync(0xffffffffu, alpha, i);
            vmax = fmaxf(vmax, ai + Tc[i]);
        }
        float s = 0.f;
#pragma unroll
        for (int i = 0; i < 32; i++) {
            float ai = __shfl_sync(0xffffffffu, alpha, i);
            s += expf(ai + Tc[i] - vmax);
        }
        float na = vmax + logf(s) + lg[(size_t)t * Ll + j];
        if (t < sl) alpha = na;
    }
    float m2 = alpha;
#pragma unroll
    for (int o = 16; o; o >>= 1) m2 = fmaxf(m2, __shfl_xor_sync(0xffffffffu, m2, o));
    float s2 = expf(alpha - m2);
#pragma unroll
    for (int o = 16; o; o >>= 1) s2 += __shfl_xor_sync(0xffffffffu, s2, o);
    if (j == 0) g_pb[b] = (m2 + logf(s2)) - gold;
}

__global__ void finalize_kernel(float* __restrict__ out)
{
    float s = 0.f;
#pragma unroll
    for (int i = 0; i < Bb; i++) s += g_pb[i];
    out[0] = s / (float)Bb;
}

// ---------------------------------------------------------------------------
// Launch
// ---------------------------------------------------------------------------
extern "C" void kernel_launch(void* const* d_in, const int* in_sizes, int n_in,
                              void* d_out, int out_size)
{
    const int* char_ids = (const int*)d_in[0];
    const int* kb_ids   = (const int*)d_in[1];
    const int* wbeg     = (const int*)d_in[2];
    const int* wlen     = (const int*)d_in[3];
    const int* label    = (const int*)d_in[4];
    const int* slen     = (const int*)d_in[5];
    const float* char_emb = (const float*)d_in[6];
    const float* kb_emb   = (const float*)d_in[7];
    const float* dense_W  = (const float*)d_in[8];
    const float* dense_b  = (const float*)d_in[9];
    const float* crf_T    = (const float*)d_in[10];

    const float* f_Wcx = (const float*)d_in[11];
    const float* f_Wch = (const float*)d_in[12];
    const float* f_bc  = (const float*)d_in[13];
    const float* f_Wwx = (const float*)d_in[14];
    const float* f_Wwh = (const float*)d_in[15];
    const float* f_bw  = (const float*)d_in[16];
    const float* f_Wlx = (const float*)d_in[17];
    const float* f_Wlc = (const float*)d_in[18];
    const float* f_bl  = (const float*)d_in[19];

    const float* r_Wcx = (const float*)d_in[20];
    const float* r_Wch = (const float*)d_in[21];
    const float* r_bc  = (const float*)d_in[22];
    const float* r_Wwx = (const float*)d_in[23];
    const float* r_Wwh = (const float*)d_in[24];
    const float* r_bw  = (const float*)d_in[25];
    const float* r_Wlx = (const float*)d_in[26];
    const float* r_Wlc = (const float*)d_in[27];
    const float* r_bl  = (const float*)d_in[28];

    prep_pack_kernel<<<dim3(192, 4), 256>>>(f_Wwh, r_Wwh, f_Wlc, r_Wlc);

    char_gather_kernel<<<dim3(Bb, Ss / 8), 256>>>(char_emb, char_ids,
        f_Wcx, r_Wcx, f_Wlx, r_Wlx, f_bc, r_bc, f_bl, r_bl);
    kb_gather_kernel<<<dim3(Bb, Nn / 8), 256>>>(kb_emb, kb_ids,
        f_Wwx, r_Wwx, f_bw, r_bw);

    cudaFuncSetAttribute(lattice_kernel, cudaFuncAttributeMaxDynamicSharedMemorySize, SMEM_LAT);
    lattice_kernel<<<2 * Bb, NTHR, SMEM_LAT>>>(f_Wch, r_Wch, wbeg, wlen, slen);

    dense_kernel<<<(Bb * Ss) / 8, 256>>>(dense_W, dense_b);
    crf_kernel<<<Bb, 32>>>(label, slen, crf_T);
    finalize_kernel<<<1, 1>>>((float*)d_out);
}

// round 9
// speedup vs baseline: 3.2902x; 1.3934x over previous
#include <cuda_runtime.h>
#include <cuda_fp16.h>
#include <math.h>

#define Bb 16
#define Ss 128
#define Nn 64
#define Ee 128
#define Hh 128
#define Ll 32

// ---------------------------------------------------------------------------
// Device-global scratch
// ---------------------------------------------------------------------------
__device__ float g_Xg[(size_t)2 * Bb * Ss * 4 * Hh];   // (dir,b,t,512)
__device__ float g_Xl[(size_t)2 * Bb * Ss * Hh];       // (dir,b,t,128)
__device__ float g_Wg[(size_t)2 * Bb * Nn * 3 * Hh];   // (dir,b,n,384)
__device__ __half g_Wwh16[(size_t)2 * 128 * 384];      // (dir, (j8*384+k)*8+i)
__device__ __half g_Wlc16[(size_t)2 * 128 * 128];      // (dir, (j8*128+k)*8+i)
__device__ float g_feats[(size_t)Bb * Ss * 2 * Hh];
__device__ float g_logits[(size_t)Bb * Ss * Ll];
__device__ float g_pb[Bb];

// fast transcendentals (~2 ulp; tolerance is 1e-3)
__device__ __forceinline__ float sigf(float x) {
    return __fdividef(1.f, 1.f + __expf(-x));
}
__device__ __forceinline__ float tanhfast(float x) {
    return 1.f - 2.f * __fdividef(1.f, __expf(2.f * x) + 1.f);
}

// accumulate 8 fp16 weights (one 16B quad = rows 8j..8j+7) against 8 fp32 h
__device__ __forceinline__ void dot8acc(float& acc, float4 hA, float4 hB, uint4 w) {
    float2 f0 = __half22float2(*reinterpret_cast<const __half2*>(&w.x));
    float2 f1 = __half22float2(*reinterpret_cast<const __half2*>(&w.y));
    float2 f2 = __half22float2(*reinterpret_cast<const __half2*>(&w.z));
    float2 f3 = __half22float2(*reinterpret_cast<const __half2*>(&w.w));
    acc = fmaf(hA.x, f0.x, acc); acc = fmaf(hA.y, f0.y, acc);
    acc = fmaf(hA.z, f1.x, acc); acc = fmaf(hA.w, f1.y, acc);
    acc = fmaf(hB.x, f2.x, acc); acc = fmaf(hB.y, f2.y, acc);
    acc = fmaf(hB.z, f3.x, acc); acc = fmaf(hB.w, f3.y, acc);
}

// ---------------------------------------------------------------------------
// Prep: pack Wwh/Wlc into fp16 8-row-quad layouts
// ---------------------------------------------------------------------------
__global__ void prep_pack_kernel(const float* __restrict__ fWwh,
                                 const float* __restrict__ rWwh,
                                 const float* __restrict__ fWlc,
                                 const float* __restrict__ rWlc)
{
    int which = blockIdx.y;
    int idx = blockIdx.x * 256 + threadIdx.x;
    if (which < 2) {
        const float* in = which ? rWwh : fWwh;
        __half* out = g_Wwh16 + (size_t)which * 128 * 384;
        if (idx < 128 * 384) {
            int j = idx / 384, k = idx - j * 384;
            out[((size_t)(j >> 3) * 384 + k) * 8 + (j & 7)] = __float2half(in[idx]);
        }
    } else {
        const float* in = (which == 3) ? rWlc : fWlc;
        __half* out = g_Wlc16 + (size_t)(which - 2) * 128 * 128;
        if (idx < 128 * 128) {
            int j = idx >> 7, k = idx & 127;
            out[((size_t)(j >> 3) * 128 + k) * 8 + (j & 7)] = __float2half(in[idx]);
        }
    }
}

// ---------------------------------------------------------------------------
// Fused char-side gather GEMM (unchanged)
// ---------------------------------------------------------------------------
__global__ void __launch_bounds__(256) char_gather_kernel(
    const float* __restrict__ emb, const int* __restrict__ ids,
    const float* __restrict__ fWcx, const float* __restrict__ rWcx,
    const float* __restrict__ fWlx, const float* __restrict__ rWlx,
    const float* __restrict__ fbc, const float* __restrict__ rbc,
    const float* __restrict__ fbl, const float* __restrict__ rbl)
{
    __shared__ float xs[8][128];
    int b = blockIdx.x, r0 = blockIdx.y * 8, tid = threadIdx.x;

    for (int idx = tid; idx < 8 * 128; idx += 256) {
        int r = idx >> 7, e = idx & 127;
        int id = ids[b * Ss + r0 + r];
        xs[r][e] = emb[(size_t)id * 128 + e];
    }
    __syncthreads();

    const float* wp[5];
    float bias[5];
    float* op[5];
    int ostep[5];

    wp[0] = fWcx + tid;        bias[0] = fbc[tid];
    wp[1] = fWcx + tid + 256;  bias[1] = fbc[tid + 256];
    op[0] = g_Xg + ((size_t)b * Ss + r0) * 512 + tid;
    op[1] = op[0] + 256;
    ostep[0] = ostep[1] = 512;
    wp[2] = rWcx + tid;        bias[2] = rbc[tid];
    wp[3] = rWcx + tid + 256;  bias[3] = rbc[tid + 256];
    op[2] = g_Xg + ((size_t)(Bb + b) * Ss + (Ss - 1 - r0)) * 512 + tid;
    op[3] = op[2] + 256;
    ostep[2] = ostep[3] = -512;
    if (tid < 128) {
        wp[4] = fWlx + tid; bias[4] = fbl[tid];
        op[4] = g_Xl + ((size_t)b * Ss + r0) * 128 + tid;
        ostep[4] = 128;
    } else {
        int c = tid - 128;
        wp[4] = rWlx + c; bias[4] = rbl[c];
        op[4] = g_Xl + ((size_t)(Bb + b) * Ss + (Ss - 1 - r0)) * 128 + c;
        ostep[4] = -128;
    }

    float acc[8][5];
#pragma unroll
    for (int r = 0; r < 8; r++)
#pragma unroll
        for (int s = 0; s < 5; s++) acc[r][s] = 0.f;

    for (int e = 0; e < 128; e++) {
        float w0 = wp[0][(size_t)e * 512];
        float w1 = wp[1][(size_t)e * 512];
        float w2 = wp[2][(size_t)e * 512];
        float w3 = wp[3][(size_t)e * 512];
        float w4 = wp[4][(size_t)e * 128];
#pragma unroll
        for (int r = 0; r < 8; r++) {
            float x = xs[r][e];
            acc[r][0] = fmaf(x, w0, acc[r][0]);
            acc[r][1] = fmaf(x, w1, acc[r][1]);
            acc[r][2] = fmaf(x, w2, acc[r][2]);
            acc[r][3] = fmaf(x, w3, acc[r][3]);
            acc[r][4] = fmaf(x, w4, acc[r][4]);
        }
    }

#pragma unroll
    for (int r = 0; r < 8; r++)
#pragma unroll
        for (int s = 0; s < 5; s++)
            op[s][(long)r * ostep[s]] = acc[r][s] + bias[s];
}

// ---------------------------------------------------------------------------
// Fused kb-side gather GEMM (unchanged)
// ---------------------------------------------------------------------------
__global__ void __launch_bounds__(256) kb_gather_kernel(
    const float* __restrict__ emb, const int* __restrict__ ids,
    const float* __restrict__ fW, const float* __restrict__ rW,
    const float* __restrict__ fb, const float* __restrict__ rb)
{
    __shared__ float xs[8][128];
    int b = blockIdx.x, r0 = blockIdx.y * 8, tid = threadIdx.x;

    for (int idx = tid; idx < 8 * 128; idx += 256) {
        int r = idx >> 7, e = idx & 127;
        int id = ids[b * Nn + r0 + r];
        xs[r][e] = emb[(size_t)id * 128 + e];
    }
    __syncthreads();

    const float* wp[3];
    float bias[3];
    float* op[3];
#pragma unroll
    for (int s = 0; s < 3; s++) {
        int c = tid + 256 * s;
        if (c < 384) {
            wp[s] = fW + c; bias[s] = fb[c];
            op[s] = g_Wg + ((size_t)b * Nn + r0) * 384 + c;
        } else {
            int c2 = c - 384;
            wp[s] = rW + c2; bias[s] = rb[c2];
            op[s] = g_Wg + ((size_t)(Bb + b) * Nn + r0) * 384 + c2;
        }
    }

    float acc[8][3];
#pragma unroll
    for (int r = 0; r < 8; r++)
#pragma unroll
        for (int s = 0; s < 3; s++) acc[r][s] = 0.f;

    for (int e = 0; e < 128; e++) {
        float w0 = wp[0][(size_t)e * 384];
        float w1 = wp[1][(size_t)e * 384];
        float w2 = wp[2][(size_t)e * 384];
#pragma unroll
        for (int r = 0; r < 8; r++) {
            float x = xs[r][e];
            acc[r][0] = fmaf(x, w0, acc[r][0]);
            acc[r][1] = fmaf(x, w1, acc[r][1]);
            acc[r][2] = fmaf(x, w2, acc[r][2]);
        }
    }

#pragma unroll
    for (int r = 0; r < 8; r++)
#pragma unroll
        for (int s = 0; s < 3; s++)
            op[s][(size_t)r * 384] = acc[r][s] + bias[s];
}

// ---------------------------------------------------------------------------
// Lattice LSTM: 640 threads/CTA.
//   threads 0-511  : HFMA2 char matvec (Wch fp16 in regs, h as half2 ring);
//                    tid<128 also do the cell update (no cross-group barrier).
//   threads 512-639: FREE-RUNNING word pipeline — words depend only on state
//                    at their begin step; cw/ew vectors stored in smem, the
//                    update just sums them. Sync via smem spin flags.
// ---------------------------------------------------------------------------
#define NTHR 640

// smem BYTE offsets (all 16B aligned)
#define OFF_WWH   0                    // 98304
#define OFF_WLC   98304                // 32768
#define OFF_H32   131072               // 8*128 f32 = 4096
#define OFF_C32   135168               // 4096
#define OFF_H2    139264               // 8*128 fp16 = 2048
#define OFF_G     141312               // 512 f32 = 2048
#define OFF_CWS   143360               // 64*128 f32 = 32768
#define OFF_EWS   176128               // 32768
#define OFF_INT   208896               // 451 ints
#define SMEM_LAT  210704

__global__ void __launch_bounds__(NTHR, 1) lattice_kernel(
    const float* __restrict__ Wch_f, const float* __restrict__ Wch_r,
    const int* __restrict__ word_begin, const int* __restrict__ word_len,
    const int* __restrict__ seqlen)
{
    extern __shared__ char smraw[];
    __half* wwh_h   = (__half*)(smraw + OFF_WWH);
    __half* wlc_h   = (__half*)(smraw + OFF_WLC);
    float* h_ring   = (float*)(smraw + OFF_H32);
    float* c_ring   = (float*)(smraw + OFF_C32);
    __half* h2r     = (__half*)(smraw + OFF_H2);
    float* gates    = (float*)(smraw + OFF_G);
    float* cw_store = (float*)(smraw + OFF_CWS);
    float* ew_store = (float*)(smraw + OFF_EWS);
    int* ip        = (int*)(smraw + OFF_INT);
    int* w_beg     = ip;            // 64
    int* w_end     = ip + 64;       // 64
    int* el_start  = ip + 128;      // 129 (cumulative by END step)
    int* el_idx    = ip + 257;      // 64  (words sorted by end)
    int* cur       = ip + 321;      // 128
    volatile int* step_flag  = (volatile int*)(ip + 449);
    volatile int* words_done = (volatile int*)(ip + 450);

    int dirb = blockIdx.x;
    int dir  = dirb / Bb;
    int b    = dirb - dir * Bb;
    int tid  = threadIdx.x;
    int sl   = seqlen[b];

    const float* Wch  = dir ? Wch_r : Wch_f;
    const float* Xg_b = g_Xg + (size_t)dirb * Ss * 512;
    const float* Xl_b = g_Xl + (size_t)dirb * Ss * 128;
    const float* Wg_b = g_Wg + (size_t)dirb * Nn * 384;

    // copy prepacked Wwh/Wlc fp16 into smem
    {
        const uint4* src = (const uint4*)(g_Wwh16 + (size_t)dir * 128 * 384);
        uint4* dst = (uint4*)wwh_h;
        for (int i = tid; i < 128 * 384 / 8; i += NTHR) dst[i] = src[i];
        const uint4* src2 = (const uint4*)(g_Wlc16 + (size_t)dir * 128 * 128);
        uint4* dst2 = (uint4*)wlc_h;
        for (int i = tid; i < 128 * 128 / 8; i += NTHR) dst2[i] = src2[i];
    }

    // ALL 128 Wch rows for column tid -> 64 half2 regs (char threads);
    // wh[i] holds rows (2i, 2i+1)
    __half2 wh[64];
    if (tid < 512) {
#pragma unroll
        for (int j = 0; j < 64; j++)
            wh[j] = __floats2half2_rn(Wch[(size_t)(2 * j) * 512 + tid],
                                      Wch[(size_t)(2 * j + 1) * 512 + tid]);
    }

    int t0 = dir ? (Ss - sl) : 0;
    int t1 = dir ? Ss : sl;

    if (tid < 128) {
        int s0 = (t0 & 7) * Hh;
        h_ring[s0 + tid] = 0.f;
        c_ring[s0 + tid] = 0.f;
        h2r[s0 + tid] = __float2half(0.f);
    }

    // zero masked feats rows
    for (int i = tid; i < (Ss - sl) * Hh; i += NTHR) {
        int row = sl + (i >> 7), col = i & 127;
        g_feats[((size_t)b * Ss + row) * (2 * Hh) + dir * Hh + col] = 0.f;
    }

    if (tid < Nn) {
        int bg = word_begin[b * Nn + tid];
        int ln = word_len[b * Nn + tid];
        int ef = min(bg + ln, Ss - 1);
        bool valid = ef < sl;
        if (dir == 0) {
            w_beg[tid] = bg;
            w_end[tid] = valid ? ef : -1;
        } else {
            w_beg[tid] = Ss - 1 - ef;
            w_end[tid] = valid ? (Ss - 1 - bg) : -1;
        }
    }
    __syncthreads();

    if (tid == 0) {
        for (int t = 0; t < Ss; t++) cur[t] = 0;
        for (int n = 0; n < Nn; n++) { int e = w_end[n]; if (e >= 0) cur[e]++; }
        el_start[0] = 0;
        for (int t = 0; t < Ss; t++) el_start[t + 1] = el_start[t] + cur[t];
        for (int t = 0; t < Ss; t++) cur[t] = el_start[t];
        for (int n = 0; n < Nn; n++) { int e = w_end[n]; if (e >= 0) el_idx[cur[e]++] = n; }
        *step_flag = t0;     // state slot t0 is ready
        *words_done = 0;
    }
    __syncthreads();

    if (tid >= 512) {
        // ================= free-running word pipeline =================
        int wt = tid - 512;
        const uint4* ww = (const uint4*)wwh_h;
        const uint4* wl = (const uint4*)wlc_h;
        int total = el_start[Ss];
        for (int wv = 0; wv < total; wv++) {
            int n  = el_idx[wv];
            int bg = w_beg[n];
            int e  = w_end[n];
            // wait until state at begin step is written
            while (*step_flag < bg) { }
            __threadfence_block();
            int bgS = (bg & 7) * Hh;
            const float4* hb4 = (const float4*)(h_ring + bgS);
            float acc0 = __ldg(Wg_b + (size_t)n * 384 + wt);
            float acc1 = __ldg(Wg_b + (size_t)n * 384 + wt + 128);
            float acc2 = __ldg(Wg_b + (size_t)n * 384 + wt + 256);
#pragma unroll 4
            for (int j8 = 0; j8 < 16; j8++) {
                float4 hA = hb4[2 * j8], hB = hb4[2 * j8 + 1];
                dot8acc(acc0, hA, hB, ww[j8 * 384 + wt]);
                dot8acc(acc1, hA, hB, ww[j8 * 384 + wt + 128]);
                dot8acc(acc2, hA, hB, ww[j8 * 384 + wt + 256]);
            }
            float cwv = sigf(acc1) * c_ring[bgS + wt] + sigf(acc0) * tanhfast(acc2);
            cw_store[n * 128 + wt] = cwv;
            asm volatile("bar.sync 1, 128;" ::: "memory");   // cw vector complete
            const float4* c4 = (const float4*)(cw_store + n * 128);
            float q0 = 0.f, q1 = 0.f;
#pragma unroll 4
            for (int j8 = 0; j8 < 16; j8 += 2) {
                dot8acc(q0, c4[2 * j8],     c4[2 * j8 + 1], wl[j8 * 128 + wt]);
                dot8acc(q1, c4[2 * j8 + 2], c4[2 * j8 + 3], wl[(j8 + 1) * 128 + wt]);
            }
            float ew = __expf(sigf(__ldg(Xl_b + (size_t)e * 128 + wt) + q0 + q1));
            ew_store[n * 128 + wt] = ew;
            asm volatile("bar.sync 1, 128;" ::: "memory");   // stores complete
            if (wt == 0) *words_done = wv + 1;
        }
    } else {
        // ================= step-locked char + update =================
        float xg = Xg_b[(size_t)t0 * 512 + tid];
        int gt = tid >> 7;   // 0,1,2 sigmoid; 3 tanh (warp-uniform)
        const __half2 hz = __floats2half2_rn(0.f, 0.f);

        for (int t = t0; t < t1; t++) {
            int curS = (t & 7) * Hh;
            int nxtS = ((t + 1) & 7) * Hh;

            asm volatile("bar.sync 4, 512;" ::: "memory");   // state t ready
            float xg_cur = xg;
            if (t + 1 < t1) xg = Xg_b[(size_t)(t + 1) * 512 + tid];

            // HFMA2 matvec: h from half2 ring, weights in regs; 4 chains
            const uint4* h2q = (const uint4*)(h2r + curS);
            __half2 a0 = hz, a1 = hz, a2 = hz, a3 = hz;
#pragma unroll
            for (int q = 0; q < 16; q++) {
                uint4 hv = h2q[q];
                a0 = __hfma2(*reinterpret_cast<const __half2*>(&hv.x), wh[4 * q + 0], a0);
                a1 = __hfma2(*reinterpret_cast<const __half2*>(&hv.y), wh[4 * q + 1], a1);
                a2 = __hfma2(*reinterpret_cast<const __half2*>(&hv.z), wh[4 * q + 2], a2);
                a3 = __hfma2(*reinterpret_cast<const __half2*>(&hv.w), wh[4 * q + 3], a3);
            }
            float2 f0 = __half22float2(a0);
            float2 f1 = __half22float2(a1);
            float2 f2 = __half22float2(a2);
            float2 f3 = __half22float2(a3);
            float gv = xg_cur + ((f0.x + f0.y) + (f1.x + f1.y))
                              + ((f2.x + f2.y) + (f3.x + f3.y));
            gates[tid] = (gt == 3) ? tanhfast(gv) : sigf(gv);
            asm volatile("bar.sync 4, 512;" ::: "memory");   // gates ready

            if (tid < 128) {
                int wls = el_start[t];
                int m = el_start[t + 1] - wls;
                float ig = gates[tid];
                float fg = gates[Hh + tid];
                float og = gates[2 * Hh + tid];
                float gg = gates[3 * Hh + tid];
                float cp = c_ring[curS + tid];
                float ct;
                if (m > 0) {
                    int target = wls + m;
                    while (*words_done < target) { }
                    __threadfence_block();
                    float sew = 0.f, sewc = 0.f;
                    for (int wv = 0; wv < m; wv++) {
                        int n = el_idx[wls + wv];
                        float ew = ew_store[n * 128 + tid];
                        sew  += ew;
                        sewc += ew * cw_store[n * 128 + tid];
                    }
                    float ec = __expf(ig);
                    ct = __fdividef(ec * gg + sewc, ec + sew);
                } else {
                    ct = fg * cp + ig * gg;
                }
                float ht = og * tanhfast(ct);
                h_ring[nxtS + tid] = ht;
                c_ring[nxtS + tid] = ct;
                h2r[nxtS + tid] = __float2half(ht);
                int tt = (dir == 0) ? t : (Ss - 1 - t);
                g_feats[((size_t)b * Ss + tt) * (2 * Hh) + dir * Hh + tid] = ht;
                asm volatile("bar.sync 5, 128;" ::: "memory");  // state stores drained
                if (tid == 0) *step_flag = t + 1;
            }
        }
    }
}

// ---------------------------------------------------------------------------
// Dense projection
// ---------------------------------------------------------------------------
__global__ void dense_kernel(const float* __restrict__ W, const float* __restrict__ bias)
{
    __shared__ float fs[8][2 * Hh];
    int row0 = blockIdx.x * 8;
    int tid = threadIdx.x;
    for (int idx = tid; idx < 8 * 2 * Hh; idx += 256) {
        int r = idx >> 8;
        int e = idx & 255;
        fs[r][e] = g_feats[(size_t)(row0 + r) * (2 * Hh) + e];
    }
    __syncthreads();
    int r = tid >> 5;
    int col = tid & 31;
    float acc = bias[col];
#pragma unroll 8
    for (int e = 0; e < 2 * Hh; e++) acc = fmaf(fs[r][e], W[e * Ll + col], acc);
    g_logits[(size_t)(row0 + r) * Ll + col] = acc;
}

// ---------------------------------------------------------------------------
// CRF
// ---------------------------------------------------------------------------
__global__ void crf_kernel(const int* __restrict__ label,
                           const int* __restrict__ seqlen,
                           const float* __restrict__ T)
{
    int b = blockIdx.x;
    int j = threadIdx.x;
    int sl = seqlen[b];
    const float* lg = g_logits + (size_t)b * Ss * Ll;
    const int*   lab = label + b * Ss;

    float Tc[32];
#pragma unroll
    for (int i = 0; i < 32; i++) Tc[i] = T[i * Ll + j];

    float gold = 0.f;
    for (int t = j; t < Ss; t += 32)
        if (t < sl) gold += lg[t * Ll + lab[t]];
    for (int t = j + 1; t < Ss; t += 32)
        if (t < sl) gold += T[lab[t - 1] * Ll + lab[t]];
#pragma unroll
    for (int o = 16; o; o >>= 1) gold += __shfl_xor_sync(0xffffffffu, gold, o);

    float alpha = lg[j];
    for (int t = 1; t < Ss; t++) {
        float vmax = -1e30f;
#pragma unroll
        for (int i = 0; i < 32; i++) {
            float ai = __shfl_sync(0xffffffffu, alpha, i);
            vmax = fmaxf(vmax, ai + Tc[i]);
        }
        float s = 0.f;
#pragma unroll
        for (int i = 0; i < 32; i++) {
            float ai = __shfl_sync(0xffffffffu, alpha, i);
            s += expf(ai + Tc[i] - vmax);
        }
        float na = vmax + logf(s) + lg[(size_t)t * Ll + j];
        if (t < sl) alpha = na;
    }
    float m2 = alpha;
#pragma unroll
    for (int o = 16; o; o >>= 1) m2 = fmaxf(m2, __shfl_xor_sync(0xffffffffu, m2, o));
    float s2 = expf(alpha - m2);
#pragma unroll
    for (int o = 16; o; o >>= 1) s2 += __shfl_xor_sync(0xffffffffu, s2, o);
    if (j == 0) g_pb[b] = (m2 + logf(s2)) - gold;
}

__global__ void finalize_kernel(float* __restrict__ out)
{
    float s = 0.f;
#pragma unroll
    for (int i = 0; i < Bb; i++) s += g_pb[i];
    out[0] = s / (float)Bb;
}

// ---------------------------------------------------------------------------
// Launch
// ---------------------------------------------------------------------------
extern "C" void kernel_launch(void* const* d_in, const int* in_sizes, int n_in,
                              void* d_out, int out_size)
{
    const int* char_ids = (const int*)d_in[0];
    const int* kb_ids   = (const int*)d_in[1];
    const int* wbeg     = (const int*)d_in[2];
    const int* wlen     = (const int*)d_in[3];
    const int* label    = (const int*)d_in[4];
    const int* slen     = (const int*)d_in[5];
    const float* char_emb = (const float*)d_in[6];
    const float* kb_emb   = (const float*)d_in[7];
    const float* dense_W  = (const float*)d_in[8];
    const float* dense_b  = (const float*)d_in[9];
    const float* crf_T    = (const float*)d_in[10];

    const float* f_Wcx = (const float*)d_in[11];
    const float* f_Wch = (const float*)d_in[12];
    const float* f_bc  = (const float*)d_in[13];
    const float* f_Wwx = (const float*)d_in[14];
    const float* f_Wwh = (const float*)d_in[15];
    const float* f_bw  = (const float*)d_in[16];
    const float* f_Wlx = (const float*)d_in[17];
    const float* f_Wlc = (const float*)d_in[18];
    const float* f_bl  = (const float*)d_in[19];

    const float* r_Wcx = (const float*)d_in[20];
    const float* r_Wch = (const float*)d_in[21];
    const float* r_bc  = (const float*)d_in[22];
    const float* r_Wwx = (const float*)d_in[23];
    const float* r_Wwh = (const float*)d_in[24];
    const float* r_bw  = (const float*)d_in[25];
    const float* r_Wlx = (const float*)d_in[26];
    const float* r_Wlc = (const float*)d_in[27];
    const float* r_bl  = (const float*)d_in[28];

    prep_pack_kernel<<<dim3(192, 4), 256>>>(f_Wwh, r_Wwh, f_Wlc, r_Wlc);

    char_gather_kernel<<<dim3(Bb, Ss / 8), 256>>>(char_emb, char_ids,
        f_Wcx, r_Wcx, f_Wlx, r_Wlx, f_bc, r_bc, f_bl, r_bl);
    kb_gather_kernel<<<dim3(Bb, Nn / 8), 256>>>(kb_emb, kb_ids,
        f_Wwx, r_Wwx, f_bw, r_bw);

    cudaFuncSetAttribute(lattice_kernel, cudaFuncAttributeMaxDynamicSharedMemorySize, SMEM_LAT);
    lattice_kernel<<<2 * Bb, NTHR, SMEM_LAT>>>(f_Wch, r_Wch, wbeg, wlen, slen);

    dense_kernel<<<(Bb * Ss) / 8, 256>>>(dense_W, dense_b);
    crf_kernel<<<Bb, 32>>>(label, slen, crf_T);
    finalize_kernel<<<1, 1>>>((float*)d_out);
}